// round 11
// baseline (speedup 1.0000x reference)
#include <cuda_runtime.h>
#include <cuda_bf16.h>
#include <cstdint>

#define BB 8
#define SS 4096
#define DD 1024
#define MM 32
#define KA 3
#define RR 64
#define NROWS (BB*SS)

// ---------------- scratch (device globals; no allocations allowed) ----------------
__device__ float g_scores[NROWS];
__device__ int   g_aidx[BB*KA];
__device__ float g_apos[BB*KA];
__device__ float g_logits[BB*KA*MM];
__device__ float g_ua[BB*KA*MM*RR];
__device__ float g_w[BB*KA*MM];
__device__ float g_low[BB*KA*RR];
__device__ float g_Z[BB*KA];
__device__ float g_transp[BB*KA*MM*DD];
__device__ float g_trans[BB*KA*DD];
__device__ float g_tsaug[(size_t)NROWS*DD];
__device__ float g_gate[NROWS];
__device__ float g_shared[(size_t)NROWS*DD];
__device__ __align__(16) __nv_bfloat16 g_cat[(size_t)NROWS*2*DD];   // [tsn|ptn] bf16
__device__ __align__(16) __nv_bfloat16 g_a2[(size_t)NROWS*DD];
__device__ __align__(16) __nv_bfloat16 g_a3[(size_t)NROWS*DD];
__device__ __align__(16) __nv_bfloat16 g_w1[(size_t)2048*DD];       // shared_W[0:2048] bf16
__device__ __align__(16) __nv_bfloat16 g_w2[(size_t)DD*DD];         // ts_up_W bf16
__device__ __align__(16) __nv_bfloat16 g_w3[(size_t)DD*DD];         // pt_up_W bf16

// ---------------- cp.async helpers ----------------
__device__ __forceinline__ void cp16s(unsigned int dst_sh, const void* src) {
    asm volatile("cp.async.cg.shared.global [%0], [%1], 16;\n" :: "r"(dst_sh), "l"(src));
}
#define CP_COMMIT() asm volatile("cp.async.commit_group;\n" ::: "memory")
#define CP_WAIT1()  asm volatile("cp.async.wait_group 1;\n" ::: "memory")
#define CP_WAIT0()  asm volatile("cp.async.wait_group 0;\n" ::: "memory")

// ---------------- weight fp32 -> bf16 ----------------
__global__ void __launch_bounds__(256) k_cvt(const float* __restrict__ src,
                                             __nv_bfloat16* __restrict__ dst, int n4) {
    int i = blockIdx.x * blockDim.x + threadIdx.x;
    if (i >= n4) return;
    float4 v = ((const float4*)src)[i];
    __nv_bfloat162* o = (__nv_bfloat162*)dst + i * 2;
    o[0] = __floats2bfloat162_rn(v.x, v.y);
    o[1] = __floats2bfloat162_rn(v.z, v.w);
}

// ---------------- K0: anchor scores ----------------
__global__ void __launch_bounds__(256) k_scores(const float* __restrict__ pt,
                                                const float* __restrict__ aw,
                                                const float* __restrict__ ab) {
    int gw = (blockIdx.x * blockDim.x + threadIdx.x) >> 5;
    int lane = threadIdx.x & 31;
    if (gw >= NROWS) return;
    const float4* p = (const float4*)(pt + (size_t)gw * DD);
    const float4* w = (const float4*)aw;
    float s = 0.f;
#pragma unroll
    for (int i = 0; i < 8; i++) {
        float4 a = p[lane + 32 * i];
        float4 b = w[lane + 32 * i];
        s += a.x * b.x + a.y * b.y + a.z * b.z + a.w * b.w;
    }
#pragma unroll
    for (int o = 16; o; o >>= 1) s += __shfl_down_sync(0xffffffffu, s, o);
    if (!lane) g_scores[gw] = s + ab[0];
}

// ---------------- K1: top-3 per batch ----------------
__global__ void k_top3(const float* __restrict__ pos) {
    __shared__ float sv[256];
    __shared__ int   si[256];
    __shared__ int   chosen[KA];
    int b = blockIdx.x, tid = threadIdx.x;
    const float* sc = g_scores + b * SS;
    for (int k = 0; k < KA; k++) {
        float bv = -3.4e38f; int bi = SS;
        for (int s = tid; s < SS; s += 256) {
            bool used = false;
            for (int j = 0; j < k; j++) used |= (chosen[j] == s);
            if (used) continue;
            float v = sc[s];
            if (v > bv || (v == bv && s < bi)) { bv = v; bi = s; }
        }
        sv[tid] = bv; si[tid] = bi;
        __syncthreads();
        for (int o = 128; o; o >>= 1) {
            if (tid < o) {
                if (sv[tid + o] > sv[tid] || (sv[tid + o] == sv[tid] && si[tid + o] < si[tid])) {
                    sv[tid] = sv[tid + o]; si[tid] = si[tid + o];
                }
            }
            __syncthreads();
        }
        if (tid == 0) {
            chosen[k] = si[0];
            g_aidx[b * KA + k] = si[0];
            g_apos[b * KA + k] = pos[si[0]];
        }
        __syncthreads();
    }
}

// ---------------- K2: per (b,k,m): cosine logit + u_a ----------------
__global__ void __launch_bounds__(128) k_basis(const float* __restrict__ pt,
                                               const float* __restrict__ cent,
                                               const float* __restrict__ ta) {
    __shared__ float av[DD];
    __shared__ float r1[128], r2[128], r3[128];
    int id = blockIdx.x;
    int m = id % MM, bk = id / MM;
    int b = bk / KA;
    int tid = threadIdx.x;
    const float* prow = pt + ((size_t)b * SS + g_aidx[bk]) * DD;
    const float* crow = cent + (size_t)m * DD;
    float pa = 0.f, pc = 0.f, pd = 0.f;
    for (int d = tid; d < DD; d += 128) {
        float a = prow[d], c = crow[d];
        av[d] = a; pa += a * a; pc += c * c; pd += a * c;
    }
    r1[tid] = pa; r2[tid] = pc; r3[tid] = pd;
    __syncthreads();
    for (int o = 64; o; o >>= 1) {
        if (tid < o) { r1[tid] += r1[tid + o]; r2[tid] += r2[tid + o]; r3[tid] += r3[tid + o]; }
        __syncthreads();
    }
    if (tid == 0) {
        float na = sqrtf(r1[0]), nc = sqrtf(r2[0]);
        g_logits[id] = r3[0] / (fmaxf(na, 1e-6f) * fmaxf(nc, 1e-6f));
    }
    __syncthreads();
    int r = tid & 63, h = tid >> 6;
    const float* tap = ta + (size_t)m * DD * RR + r;
    float u = 0.f;
    int d0 = h * 512;
#pragma unroll 8
    for (int d = d0; d < d0 + 512; d++) u += av[d] * tap[(size_t)d * RR];
    r1[tid] = u;
    __syncthreads();
    if (h == 0) g_ua[(size_t)id * RR + r] = r1[r] + r1[r + 64];
}

// ---------------- K3: per (b,k): softmax, low, spread normalizer ----------------
__global__ void __launch_bounds__(128) k_mix(const float* __restrict__ pos) {
    __shared__ float w[MM];
    __shared__ float red[128];
    int bk = blockIdx.x, tid = threadIdx.x;
    if (tid == 0) {
        float mx = -3.4e38f;
        for (int m = 0; m < MM; m++) mx = fmaxf(mx, g_logits[bk * MM + m]);
        float ssum = 0.f;
        for (int m = 0; m < MM; m++) { float e = expf(g_logits[bk * MM + m] - mx); w[m] = e; ssum += e; }
        float inv = 1.0f / ssum;
        for (int m = 0; m < MM; m++) w[m] *= inv;
    }
    __syncthreads();
    if (tid < MM) g_w[bk * MM + tid] = w[tid];
    if (tid < RR) {
        float lo = 0.f;
        for (int m = 0; m < MM; m++) lo += w[m] * g_ua[(size_t)(bk * MM + m) * RR + tid];
        g_low[bk * RR + tid] = lo;
    }
    float p = g_apos[bk];
    float z = 0.f;
    for (int s = tid; s < SS; s += 128) {
        float d = fabsf(pos[s] - p);
        if (d <= 8.0f) z += expf(-d * 0.125f);
    }
    red[tid] = z;
    __syncthreads();
    for (int o = 64; o; o >>= 1) { if (tid < o) red[tid] += red[tid + o]; __syncthreads(); }
    if (tid == 0) g_Z[bk] = red[0];
}

// ---------------- K4: per (b,k,m): partial translated ----------------
__global__ void __launch_bounds__(128) k_translate(const float* __restrict__ tb) {
    __shared__ float low[RR];
    __shared__ float wv;
    int id = blockIdx.x;
    int m = id % MM, bk = id / MM;
    int tid = threadIdx.x;
    if (tid < RR) low[tid] = g_low[bk * RR + tid];
    if (tid == 0) wv = g_w[bk * MM + m];
    __syncthreads();
    float wloc = wv;
    const float4* base = (const float4*)(tb + (size_t)m * DD * RR);
#pragma unroll
    for (int j = 0; j < 8; j++) {
        int d = tid + 128 * j;
        const float4* rp = base + (size_t)d * (RR / 4);
        float acc = 0.f;
#pragma unroll
        for (int i = 0; i < 16; i++) {
            float4 v = rp[i];
            acc += low[4 * i] * v.x + low[4 * i + 1] * v.y + low[4 * i + 2] * v.z + low[4 * i + 3] * v.w;
        }
        g_transp[(size_t)id * DD + d] = wloc * acc;
    }
}

__global__ void __launch_bounds__(256) k_tcombine() {
    int bk = blockIdx.x, tid = threadIdx.x;
    for (int d = tid; d < DD; d += 256) {
        float s = 0.f;
        for (int m = 0; m < MM; m++) s += g_transp[(size_t)(bk * MM + m) * DD + d];
        g_trans[bk * DD + d] = s;
    }
}

// ---------------- block reduce helper ----------------
__device__ __forceinline__ float2 bred2(float2 v, float* red) {
    int tid = threadIdx.x;
#pragma unroll
    for (int o = 16; o; o >>= 1) {
        v.x += __shfl_down_sync(0xffffffffu, v.x, o);
        v.y += __shfl_down_sync(0xffffffffu, v.y, o);
    }
    if ((tid & 31) == 0) { red[tid >> 5] = v.x; red[8 + (tid >> 5)] = v.y; }
    __syncthreads();
    if (tid == 0) {
        float a = 0.f, b = 0.f;
        for (int i = 0; i < 8; i++) { a += red[i]; b += red[8 + i]; }
        red[0] = a; red[8] = b;
    }
    __syncthreads();
    float2 r = make_float2(red[0], red[8]);
    __syncthreads();
    return r;
}

// ---------------- K5: fused row kernel (anchor update + 3 LNs + gate) ----------------
__global__ void __launch_bounds__(256) k_rows(
    const float* __restrict__ ts, const float* __restrict__ pt,
    const float* __restrict__ pos, const float* __restrict__ stab,
    const float* __restrict__ og, const float* __restrict__ ob,
    const float* __restrict__ tg, const float* __restrict__ tb2,
    const float* __restrict__ pg, const float* __restrict__ pb) {
    __shared__ float red[16];
    int row = blockIdx.x;
    int b = row / SS, s = row % SS;
    int tid = threadIdx.x;
    size_t base = (size_t)row * DD;
    float4 tsv = ((const float4*)(ts + base))[tid];
    float4 ptv = ((const float4*)(pt + base))[tid];
    float ps = pos[s];
    float4 upd = make_float4(0.f, 0.f, 0.f, 0.f);
#pragma unroll
    for (int k = 0; k < KA; k++) {
        int bk = b * KA + k;
        float dist = fabsf(ps - g_apos[bk]);
        if (dist <= 8.0f) {
            float c = expf(-dist * 0.125f) / g_Z[bk];
            float4 t = ((const float4*)(g_trans + (size_t)bk * DD))[tid];
            upd.x += c * t.x; upd.y += c * t.y; upd.z += c * t.z; upd.w += c * t.w;
        }
    }
    float4 x = make_float4(tsv.x + upd.x, tsv.y + upd.y, tsv.z + upd.z, tsv.w + upd.w);
    const float invD = 1.0f / DD;
    float2 s1 = bred2(make_float2(x.x + x.y + x.z + x.w,
                                  x.x * x.x + x.y * x.y + x.z * x.z + x.w * x.w), red);
    float mu = s1.x * invD;
    float var = s1.y * invD - mu * mu;
    float rs = rsqrtf(var + 1e-5f);
    float4 gv = ((const float4*)og)[tid], bv = ((const float4*)ob)[tid];
    float4 aug;
    aug.x = (x.x - mu) * rs * gv.x + bv.x;
    aug.y = (x.y - mu) * rs * gv.y + bv.y;
    aug.z = (x.z - mu) * rs * gv.z + bv.z;
    aug.w = (x.w - mu) * rs * gv.w + bv.w;
    ((float4*)(g_tsaug + base))[tid] = aug;
    float2 s2 = bred2(make_float2(aug.x + aug.y + aug.z + aug.w,
                                  aug.x * aug.x + aug.y * aug.y + aug.z * aug.z + aug.w * aug.w), red);
    float mu2 = s2.x * invD;
    float rs2 = rsqrtf(s2.y * invD - mu2 * mu2 + 1e-5f);
    float4 gv2 = ((const float4*)tg)[tid], bv2 = ((const float4*)tb2)[tid];
    float4 tn;
    tn.x = (aug.x - mu2) * rs2 * gv2.x + bv2.x;
    tn.y = (aug.y - mu2) * rs2 * gv2.y + bv2.y;
    tn.z = (aug.z - mu2) * rs2 * gv2.z + bv2.z;
    tn.w = (aug.w - mu2) * rs2 * gv2.w + bv2.w;
    float2 s3 = bred2(make_float2(ptv.x + ptv.y + ptv.z + ptv.w,
                                  ptv.x * ptv.x + ptv.y * ptv.y + ptv.z * ptv.z + ptv.w * ptv.w), red);
    float mu3 = s3.x * invD;
    float rs3 = rsqrtf(s3.y * invD - mu3 * mu3 + 1e-5f);
    float4 gv3 = ((const float4*)pg)[tid], bv3 = ((const float4*)pb)[tid];
    float4 pn;
    pn.x = (ptv.x - mu3) * rs3 * gv3.x + bv3.x;
    pn.y = (ptv.y - mu3) * rs3 * gv3.y + bv3.y;
    pn.z = (ptv.z - mu3) * rs3 * gv3.z + bv3.z;
    pn.w = (ptv.w - mu3) * rs3 * gv3.w + bv3.w;
    {
        __nv_bfloat162* ct = (__nv_bfloat162*)(g_cat + (size_t)row * 2 * DD) + tid * 2;
        ct[0] = __floats2bfloat162_rn(tn.x, tn.y);
        ct[1] = __floats2bfloat162_rn(tn.z, tn.w);
        __nv_bfloat162* cp2 = (__nv_bfloat162*)(g_cat + (size_t)row * 2 * DD + DD) + tid * 2;
        cp2[0] = __floats2bfloat162_rn(pn.x, pn.y);
        cp2[1] = __floats2bfloat162_rn(pn.z, pn.w);
    }
    float2 s4 = bred2(make_float2(tn.x * pn.x + tn.y * pn.y + tn.z * pn.z + tn.w * pn.w,
                                  tn.x * tn.x + tn.y * tn.y + tn.z * tn.z + tn.w * tn.w), red);
    float2 s5 = bred2(make_float2(pn.x * pn.x + pn.y * pn.y + pn.z * pn.z + pn.w * pn.w, 0.f), red);
    if (tid == 0) {
        float cosv = s4.x / (fmaxf(sqrtf(s4.y), 1e-6f) * fmaxf(sqrtf(s5.x), 1e-6f));
        float ag = 0.5f * (1.0f + cosv);
        float z = (ag - 0.72f) / 0.2f;
        float focus = 0.2f + 0.8f * expf(-0.5f * z * z);
        g_gate[row] = ag * focus * stab[row];
    }
}

// ---------------- K7: causal pool + form bf16 GEMM inputs ----------------
__global__ void __launch_bounds__(256) k_pool() {
    int row = blockIdx.x;
    int b = row / SS, s = row % SS;
    int tid = threadIdx.x;
    size_t base = (size_t)row * DD;
    int s1 = s - 1; if (s1 < 0) s1 = 0;
    int s2 = s - 2; if (s2 < 0) s2 = 0;
    size_t b1 = ((size_t)b * SS + s1) * DD;
    size_t b2 = ((size_t)b * SS + s2) * DD;
    float4 x0 = ((const float4*)(g_shared + base))[tid];
    float4 x1 = ((const float4*)(g_shared + b1))[tid];
    float4 x2 = ((const float4*)(g_shared + b2))[tid];
    float4 pl;
    pl.x = (x0.x + x1.x + x2.x) / 3.0f;
    pl.y = (x0.y + x1.y + x2.y) / 3.0f;
    pl.z = (x0.z + x1.z + x2.z) / 3.0f;
    pl.w = (x0.w + x1.w + x2.w) / 3.0f;
    const __nv_bfloat162* ct = (const __nv_bfloat162*)(g_cat + (size_t)row * 2 * DD) + tid * 2;
    const __nv_bfloat162* cp2 = (const __nv_bfloat162*)(g_cat + (size_t)row * 2 * DD + DD) + tid * 2;
    float2 t01 = __bfloat1622float2(ct[0]);
    float2 t23 = __bfloat1622float2(ct[1]);
    float2 p01 = __bfloat1622float2(cp2[0]);
    float2 p23 = __bfloat1622float2(cp2[1]);
    __nv_bfloat162* o2 = (__nv_bfloat162*)(g_a2 + base) + tid * 2;
    o2[0] = __floats2bfloat162_rn(pl.x - t01.x, pl.y - t01.y);
    o2[1] = __floats2bfloat162_rn(pl.z - t23.x, pl.w - t23.y);
    __nv_bfloat162* o3 = (__nv_bfloat162*)(g_a3 + base) + tid * 2;
    o3[0] = __floats2bfloat162_rn(pl.x - p01.x, pl.y - p01.y);
    o3[1] = __floats2bfloat162_rn(pl.z - p23.x, pl.w - p23.y);
}

// ---------------- raw mma.sync bf16 GEMM ----------------
// block 128x128, BK=64, 3-stage cp.async (2 CTAs/SM), 256 threads, warp tile 32x64.
// Register double-buffered ldmatrix fragments; next-stage cp.async issued before MMAs.
// A smem: 128 rows x 128B (swizzle kc^=m&7);  B smem: 64 rows x 256B (swizzle nc^=k&15)
#define STG_BYTES 32768          // 16KB A + 16KB B per stage
#define GEMM_SMEM (3*STG_BYTES)  // 98304 -> 2 CTAs/SM

template<int MODE>
__global__ void __launch_bounds__(256) k_gemm(const __nv_bfloat16* __restrict__ A, int lda,
                                              const __nv_bfloat16* __restrict__ Bw,
                                              const float* __restrict__ bias,
                                              const float* __restrict__ wlast,
                                              const float* __restrict__ basept,
                                              const float* __restrict__ bscale,
                                              float* __restrict__ outp, int Ktot) {
    extern __shared__ char smem_raw[];
    const unsigned int sbase = (unsigned int)__cvta_generic_to_shared(smem_raw);
    const int tid = threadIdx.x, lane = tid & 31, wid = tid >> 5;
    const int wm = wid & 3, wn = wid >> 2;
    const int row0 = blockIdx.y * 128, col0 = blockIdx.x * 128;

    float acc[2][8][4];
#pragma unroll
    for (int i = 0; i < 2; i++)
#pragma unroll
        for (int j = 0; j < 8; j++)
#pragma unroll
            for (int q = 0; q < 4; q++) acc[i][j][q] = 0.0f;

    const int nIter = Ktot >> 6;

    auto load_stage = [&](int s, int kt) {
        unsigned int ab = sbase + s * STG_BYTES;
        unsigned int bb = ab + 16384;
#pragma unroll
        for (int p = 0; p < 4; p++) {
            int id = tid + 256 * p;
            int m = id >> 3, kc = id & 7;
            cp16s(ab + m * 128 + ((kc ^ (m & 7)) << 4),
                  A + (size_t)(row0 + m) * lda + kt * 64 + kc * 8);
            int k = id >> 4, nc = id & 15;
            cp16s(bb + k * 256 + ((nc ^ (k & 15)) << 4),
                  Bw + (size_t)(kt * 64 + k) * DD + col0 + nc * 8);
        }
        CP_COMMIT();
    };

    // fragment loader: fills buffer `b` for k-slice kk of the stage at (ab, bb)
    unsigned int af[2][2][4], bf[2][8][2];
    auto ldfrag = [&](int b, int kk, unsigned int ab, unsigned int bb) {
#pragma unroll
        for (int i = 0; i < 2; i++) {
            int r = wm * 32 + i * 16 + (lane & 15);
            int kc = kk * 2 + (lane >> 4);
            unsigned int addr = ab + r * 128 + ((kc ^ (r & 7)) << 4);
            asm volatile("ldmatrix.sync.aligned.m8n8.x4.shared.b16 {%0,%1,%2,%3}, [%4];"
                : "=r"(af[b][i][0]), "=r"(af[b][i][1]), "=r"(af[b][i][2]), "=r"(af[b][i][3])
                : "r"(addr));
        }
#pragma unroll
        for (int j = 0; j < 4; j++) {
            int r = kk * 16 + (lane & 7) + ((lane >> 3) & 1) * 8;
            int nc = wn * 8 + j * 2 + (lane >> 4);
            unsigned int addr = bb + r * 256 + ((nc ^ (r & 15)) << 4);
            asm volatile("ldmatrix.sync.aligned.m8n8.x4.trans.shared.b16 {%0,%1,%2,%3}, [%4];"
                : "=r"(bf[b][2*j][0]), "=r"(bf[b][2*j][1]), "=r"(bf[b][2*j+1][0]), "=r"(bf[b][2*j+1][1])
                : "r"(addr));
        }
    };

    load_stage(0, 0);
    load_stage(1, 1);

    int st = 0;
    for (int it = 0; it < nIter; it++) {
        CP_WAIT1();
        __syncthreads();
        // issue next stage's gmem loads first — a full tile of MMA work hides them
        int nf = it + 2;
        if (nf < nIter) load_stage(nf - (nf / 3) * 3, nf);
        else CP_COMMIT();
        unsigned int ab = sbase + st * STG_BYTES;
        unsigned int bb = ab + 16384;
        ldfrag(0, 0, ab, bb);
#pragma unroll
        for (int kk = 0; kk < 4; kk++) {
            int cur = kk & 1, nxt = cur ^ 1;
            if (kk < 3) ldfrag(nxt, kk + 1, ab, bb);
#pragma unroll
            for (int i = 0; i < 2; i++)
#pragma unroll
                for (int j = 0; j < 8; j++)
                    asm volatile("mma.sync.aligned.m16n8k16.row.col.f32.bf16.bf16.f32 "
                        "{%0,%1,%2,%3}, {%4,%5,%6,%7}, {%8,%9}, {%0,%1,%2,%3};"
                        : "+f"(acc[i][j][0]), "+f"(acc[i][j][1]), "+f"(acc[i][j][2]), "+f"(acc[i][j][3])
                        : "r"(af[cur][i][0]), "r"(af[cur][i][1]), "r"(af[cur][i][2]), "r"(af[cur][i][3]),
                          "r"(bf[cur][j][0]), "r"(bf[cur][j][1]));
        }
        st++; if (st == 3) st = 0;
    }

    // epilogue straight from accumulator registers
    float blend = 0.0f;
    if (MODE != 1) blend = 0.35f / (1.0f + expf(-bscale[0]));
#pragma unroll
    for (int i = 0; i < 2; i++) {
        int rb = row0 + wm * 32 + i * 16 + (lane >> 2);
#pragma unroll
        for (int h = 0; h < 2; h++) {
            int r = rb + h * 8;
            float g = g_gate[r];
            float lb = blend * g;
#pragma unroll
            for (int j = 0; j < 8; j++) {
                int c = col0 + wn * 64 + j * 8 + (lane & 3) * 2;
                float v0 = acc[i][j][h * 2], v1 = acc[i][j][h * 2 + 1];
                if (MODE == 1) {
                    float2 bi = *(const float2*)(bias + c);
                    float2 wl = *(const float2*)(wlast + c);
                    float2 o = make_float2(v0 + bi.x + g * wl.x, v1 + bi.y + g * wl.y);
                    *(float2*)(g_shared + (size_t)r * DD + c) = o;
                } else {
                    const float* bp = (MODE == 2 ? g_tsaug : basept) + (size_t)r * DD + c;
                    float2 b2 = *(const float2*)bp;
                    float2 o = make_float2(b2.x + lb * v0, b2.y + lb * v1);
                    *(float2*)(outp + (size_t)r * DD + c) = o;
                }
            }
        }
    }
}

// ---------------- launch ----------------
extern "C" void kernel_launch(void* const* d_in, const int* in_sizes, int n_in,
                              void* d_out, int out_size) {
    const float* pt   = (const float*)d_in[0];
    const float* ts   = (const float*)d_in[1];
    const float* pos  = (const float*)d_in[2];
    const float* cent = (const float*)d_in[3];
    const float* stab = (const float*)d_in[4];
    const float* aw   = (const float*)d_in[5];
    const float* ab   = (const float*)d_in[6];
    const float* ta   = (const float*)d_in[7];
    const float* tb   = (const float*)d_in[8];
    const float* og   = (const float*)d_in[9];
    const float* ob   = (const float*)d_in[10];
    const float* tg   = (const float*)d_in[11];
    const float* tb2  = (const float*)d_in[12];
    const float* pg   = (const float*)d_in[13];
    const float* pb   = (const float*)d_in[14];
    const float* sW   = (const float*)d_in[15];
    const float* sb   = (const float*)d_in[16];
    const float* tuW  = (const float*)d_in[17];
    const float* puW  = (const float*)d_in[18];
    const float* bs   = (const float*)d_in[19];
    float* out = (float*)d_out;

    cudaFuncSetAttribute(k_gemm<1>, cudaFuncAttributeMaxDynamicSharedMemorySize, GEMM_SMEM);
    cudaFuncSetAttribute(k_gemm<2>, cudaFuncAttributeMaxDynamicSharedMemorySize, GEMM_SMEM);
    cudaFuncSetAttribute(k_gemm<3>, cudaFuncAttributeMaxDynamicSharedMemorySize, GEMM_SMEM);

    __nv_bfloat16 *w1p, *w2p, *w3p;
    cudaGetSymbolAddress((void**)&w1p, g_w1);
    cudaGetSymbolAddress((void**)&w2p, g_w2);
    cudaGetSymbolAddress((void**)&w3p, g_w3);
    __nv_bfloat16 *catp, *a2p, *a3p;
    cudaGetSymbolAddress((void**)&catp, g_cat);
    cudaGetSymbolAddress((void**)&a2p, g_a2);
    cudaGetSymbolAddress((void**)&a3p, g_a3);

    // weight conversions (tiny)
    k_cvt<<<(2048 * DD / 4 + 255) / 256, 256>>>(sW, w1p, 2048 * DD / 4);
    k_cvt<<<(DD * DD / 4 + 255) / 256, 256>>>(tuW, w2p, DD * DD / 4);
    k_cvt<<<(DD * DD / 4 + 255) / 256, 256>>>(puW, w3p, DD * DD / 4);

    k_scores<<<NROWS / 8, 256>>>(pt, aw, ab);
    k_top3<<<BB, 256>>>(pos);
    k_basis<<<BB * KA * MM, 128>>>(pt, cent, ta);
    k_mix<<<BB * KA, 128>>>(pos);
    k_translate<<<BB * KA * MM, 128>>>(tb);
    k_tcombine<<<BB * KA, 256>>>();
    k_rows<<<NROWS, 256>>>(ts, pt, pos, stab, og, ob, tg, tb2, pg, pb);

    dim3 gg(8, 256);
    k_gemm<1><<<gg, 256, GEMM_SMEM>>>(catp, 2 * DD, w1p, sb, sW + (size_t)2048 * DD,
                                      nullptr, nullptr, nullptr, 2048);
    k_pool<<<NROWS, 256>>>();
    k_gemm<2><<<gg, 256, GEMM_SMEM>>>(a2p, DD, w2p, nullptr, nullptr,
                                      nullptr, bs, out, 1024);
    k_gemm<3><<<gg, 256, GEMM_SMEM>>>(a3p, DD, w3p, nullptr, nullptr,
                                      pt, bs, out + (size_t)NROWS * DD, 1024);
}

// round 12
// speedup vs baseline: 1.1541x; 1.1541x over previous
#include <cuda_runtime.h>
#include <cuda_bf16.h>
#include <cstdint>

#define BB 8
#define SS 4096
#define DD 1024
#define MM 32
#define KA 3
#define RR 64
#define NROWS (BB*SS)

// ---------------- scratch (device globals; no allocations allowed) ----------------
__device__ float g_scores[NROWS];
__device__ int   g_aidx[BB*KA];
__device__ float g_apos[BB*KA];
__device__ float g_logits[BB*KA*MM];
__device__ float g_ua[BB*KA*MM*RR];
__device__ float g_w[BB*KA*MM];
__device__ float g_low[BB*KA*RR];
__device__ float g_Z[BB*KA];
__device__ float g_transp[BB*KA*MM*DD];
__device__ float g_trans[BB*KA*DD];
__device__ float g_tsaug[(size_t)NROWS*DD];
__device__ float g_gate[NROWS];
__device__ float g_shared[(size_t)NROWS*DD];
__device__ __align__(16) __nv_bfloat16 g_cat[(size_t)NROWS*2*DD];   // [tsn|ptn] bf16
__device__ __align__(16) __nv_bfloat16 g_a2[(size_t)NROWS*DD];
__device__ __align__(16) __nv_bfloat16 g_a3[(size_t)NROWS*DD];
__device__ __align__(16) __nv_bfloat16 g_w1[(size_t)2048*DD];       // shared_W[0:2048] bf16
__device__ __align__(16) __nv_bfloat16 g_w2[(size_t)DD*DD];         // ts_up_W bf16
__device__ __align__(16) __nv_bfloat16 g_w3[(size_t)DD*DD];         // pt_up_W bf16

// ---------------- cp.async helpers ----------------
__device__ __forceinline__ void cp16s(unsigned int dst_sh, const void* src) {
    asm volatile("cp.async.cg.shared.global [%0], [%1], 16;\n" :: "r"(dst_sh), "l"(src));
}
#define CP_COMMIT() asm volatile("cp.async.commit_group;\n" ::: "memory")
#define CP_WAIT1()  asm volatile("cp.async.wait_group 1;\n" ::: "memory")
#define CP_WAIT0()  asm volatile("cp.async.wait_group 0;\n" ::: "memory")

// ---------------- weight fp32 -> bf16 ----------------
__global__ void __launch_bounds__(256) k_cvt(const float* __restrict__ src,
                                             __nv_bfloat16* __restrict__ dst, int n4) {
    int i = blockIdx.x * blockDim.x + threadIdx.x;
    if (i >= n4) return;
    float4 v = ((const float4*)src)[i];
    __nv_bfloat162* o = (__nv_bfloat162*)dst + i * 2;
    o[0] = __floats2bfloat162_rn(v.x, v.y);
    o[1] = __floats2bfloat162_rn(v.z, v.w);
}

// ---------------- K0: anchor scores ----------------
__global__ void __launch_bounds__(256) k_scores(const float* __restrict__ pt,
                                                const float* __restrict__ aw,
                                                const float* __restrict__ ab) {
    int gw = (blockIdx.x * blockDim.x + threadIdx.x) >> 5;
    int lane = threadIdx.x & 31;
    if (gw >= NROWS) return;
    const float4* p = (const float4*)(pt + (size_t)gw * DD);
    const float4* w = (const float4*)aw;
    float s = 0.f;
#pragma unroll
    for (int i = 0; i < 8; i++) {
        float4 a = p[lane + 32 * i];
        float4 b = w[lane + 32 * i];
        s += a.x * b.x + a.y * b.y + a.z * b.z + a.w * b.w;
    }
#pragma unroll
    for (int o = 16; o; o >>= 1) s += __shfl_down_sync(0xffffffffu, s, o);
    if (!lane) g_scores[gw] = s + ab[0];
}

// ---------------- K1: top-3 per batch ----------------
__global__ void k_top3(const float* __restrict__ pos) {
    __shared__ float sv[256];
    __shared__ int   si[256];
    __shared__ int   chosen[KA];
    int b = blockIdx.x, tid = threadIdx.x;
    const float* sc = g_scores + b * SS;
    for (int k = 0; k < KA; k++) {
        float bv = -3.4e38f; int bi = SS;
        for (int s = tid; s < SS; s += 256) {
            bool used = false;
            for (int j = 0; j < k; j++) used |= (chosen[j] == s);
            if (used) continue;
            float v = sc[s];
            if (v > bv || (v == bv && s < bi)) { bv = v; bi = s; }
        }
        sv[tid] = bv; si[tid] = bi;
        __syncthreads();
        for (int o = 128; o; o >>= 1) {
            if (tid < o) {
                if (sv[tid + o] > sv[tid] || (sv[tid + o] == sv[tid] && si[tid + o] < si[tid])) {
                    sv[tid] = sv[tid + o]; si[tid] = si[tid + o];
                }
            }
            __syncthreads();
        }
        if (tid == 0) {
            chosen[k] = si[0];
            g_aidx[b * KA + k] = si[0];
            g_apos[b * KA + k] = pos[si[0]];
        }
        __syncthreads();
    }
}

// ---------------- K2: per (b,k,m): cosine logit + u_a ----------------
__global__ void __launch_bounds__(128) k_basis(const float* __restrict__ pt,
                                               const float* __restrict__ cent,
                                               const float* __restrict__ ta) {
    __shared__ float av[DD];
    __shared__ float r1[128], r2[128], r3[128];
    int id = blockIdx.x;
    int m = id % MM, bk = id / MM;
    int b = bk / KA;
    int tid = threadIdx.x;
    const float* prow = pt + ((size_t)b * SS + g_aidx[bk]) * DD;
    const float* crow = cent + (size_t)m * DD;
    float pa = 0.f, pc = 0.f, pd = 0.f;
    for (int d = tid; d < DD; d += 128) {
        float a = prow[d], c = crow[d];
        av[d] = a; pa += a * a; pc += c * c; pd += a * c;
    }
    r1[tid] = pa; r2[tid] = pc; r3[tid] = pd;
    __syncthreads();
    for (int o = 64; o; o >>= 1) {
        if (tid < o) { r1[tid] += r1[tid + o]; r2[tid] += r2[tid + o]; r3[tid] += r3[tid + o]; }
        __syncthreads();
    }
    if (tid == 0) {
        float na = sqrtf(r1[0]), nc = sqrtf(r2[0]);
        g_logits[id] = r3[0] / (fmaxf(na, 1e-6f) * fmaxf(nc, 1e-6f));
    }
    __syncthreads();
    int r = tid & 63, h = tid >> 6;
    const float* tap = ta + (size_t)m * DD * RR + r;
    float u = 0.f;
    int d0 = h * 512;
#pragma unroll 8
    for (int d = d0; d < d0 + 512; d++) u += av[d] * tap[(size_t)d * RR];
    r1[tid] = u;
    __syncthreads();
    if (h == 0) g_ua[(size_t)id * RR + r] = r1[r] + r1[r + 64];
}

// ---------------- K3: per (b,k): softmax, low, spread normalizer ----------------
__global__ void __launch_bounds__(128) k_mix(const float* __restrict__ pos) {
    __shared__ float w[MM];
    __shared__ float red[128];
    int bk = blockIdx.x, tid = threadIdx.x;
    if (tid == 0) {
        float mx = -3.4e38f;
        for (int m = 0; m < MM; m++) mx = fmaxf(mx, g_logits[bk * MM + m]);
        float ssum = 0.f;
        for (int m = 0; m < MM; m++) { float e = expf(g_logits[bk * MM + m] - mx); w[m] = e; ssum += e; }
        float inv = 1.0f / ssum;
        for (int m = 0; m < MM; m++) w[m] *= inv;
    }
    __syncthreads();
    if (tid < MM) g_w[bk * MM + tid] = w[tid];
    if (tid < RR) {
        float lo = 0.f;
        for (int m = 0; m < MM; m++) lo += w[m] * g_ua[(size_t)(bk * MM + m) * RR + tid];
        g_low[bk * RR + tid] = lo;
    }
    float p = g_apos[bk];
    float z = 0.f;
    for (int s = tid; s < SS; s += 128) {
        float d = fabsf(pos[s] - p);
        if (d <= 8.0f) z += expf(-d * 0.125f);
    }
    red[tid] = z;
    __syncthreads();
    for (int o = 64; o; o >>= 1) { if (tid < o) red[tid] += red[tid + o]; __syncthreads(); }
    if (tid == 0) g_Z[bk] = red[0];
}

// ---------------- K4: per (b,k,m): partial translated ----------------
__global__ void __launch_bounds__(128) k_translate(const float* __restrict__ tb) {
    __shared__ float low[RR];
    __shared__ float wv;
    int id = blockIdx.x;
    int m = id % MM, bk = id / MM;
    int tid = threadIdx.x;
    if (tid < RR) low[tid] = g_low[bk * RR + tid];
    if (tid == 0) wv = g_w[bk * MM + m];
    __syncthreads();
    float wloc = wv;
    const float4* base = (const float4*)(tb + (size_t)m * DD * RR);
#pragma unroll
    for (int j = 0; j < 8; j++) {
        int d = tid + 128 * j;
        const float4* rp = base + (size_t)d * (RR / 4);
        float acc = 0.f;
#pragma unroll
        for (int i = 0; i < 16; i++) {
            float4 v = rp[i];
            acc += low[4 * i] * v.x + low[4 * i + 1] * v.y + low[4 * i + 2] * v.z + low[4 * i + 3] * v.w;
        }
        g_transp[(size_t)id * DD + d] = wloc * acc;
    }
}

__global__ void __launch_bounds__(256) k_tcombine() {
    int bk = blockIdx.x, tid = threadIdx.x;
    for (int d = tid; d < DD; d += 256) {
        float s = 0.f;
        for (int m = 0; m < MM; m++) s += g_transp[(size_t)(bk * MM + m) * DD + d];
        g_trans[bk * DD + d] = s;
    }
}

// ---------------- block reduce helper ----------------
__device__ __forceinline__ float2 bred2(float2 v, float* red) {
    int tid = threadIdx.x;
#pragma unroll
    for (int o = 16; o; o >>= 1) {
        v.x += __shfl_down_sync(0xffffffffu, v.x, o);
        v.y += __shfl_down_sync(0xffffffffu, v.y, o);
    }
    if ((tid & 31) == 0) { red[tid >> 5] = v.x; red[8 + (tid >> 5)] = v.y; }
    __syncthreads();
    if (tid == 0) {
        float a = 0.f, b = 0.f;
        for (int i = 0; i < 8; i++) { a += red[i]; b += red[8 + i]; }
        red[0] = a; red[8] = b;
    }
    __syncthreads();
    float2 r = make_float2(red[0], red[8]);
    __syncthreads();
    return r;
}

// ---------------- K5: fused row kernel (anchor update + 3 LNs + gate) ----------------
__global__ void __launch_bounds__(256) k_rows(
    const float* __restrict__ ts, const float* __restrict__ pt,
    const float* __restrict__ pos, const float* __restrict__ stab,
    const float* __restrict__ og, const float* __restrict__ ob,
    const float* __restrict__ tg, const float* __restrict__ tb2,
    const float* __restrict__ pg, const float* __restrict__ pb) {
    __shared__ float red[16];
    int row = blockIdx.x;
    int b = row / SS, s = row % SS;
    int tid = threadIdx.x;
    size_t base = (size_t)row * DD;
    float4 tsv = ((const float4*)(ts + base))[tid];
    float4 ptv = ((const float4*)(pt + base))[tid];
    float ps = pos[s];
    float4 upd = make_float4(0.f, 0.f, 0.f, 0.f);
#pragma unroll
    for (int k = 0; k < KA; k++) {
        int bk = b * KA + k;
        float dist = fabsf(ps - g_apos[bk]);
        if (dist <= 8.0f) {
            float c = expf(-dist * 0.125f) / g_Z[bk];
            float4 t = ((const float4*)(g_trans + (size_t)bk * DD))[tid];
            upd.x += c * t.x; upd.y += c * t.y; upd.z += c * t.z; upd.w += c * t.w;
        }
    }
    float4 x = make_float4(tsv.x + upd.x, tsv.y + upd.y, tsv.z + upd.z, tsv.w + upd.w);
    const float invD = 1.0f / DD;
    float2 s1 = bred2(make_float2(x.x + x.y + x.z + x.w,
                                  x.x * x.x + x.y * x.y + x.z * x.z + x.w * x.w), red);
    float mu = s1.x * invD;
    float var = s1.y * invD - mu * mu;
    float rs = rsqrtf(var + 1e-5f);
    float4 gv = ((const float4*)og)[tid], bv = ((const float4*)ob)[tid];
    float4 aug;
    aug.x = (x.x - mu) * rs * gv.x + bv.x;
    aug.y = (x.y - mu) * rs * gv.y + bv.y;
    aug.z = (x.z - mu) * rs * gv.z + bv.z;
    aug.w = (x.w - mu) * rs * gv.w + bv.w;
    ((float4*)(g_tsaug + base))[tid] = aug;
    float2 s2 = bred2(make_float2(aug.x + aug.y + aug.z + aug.w,
                                  aug.x * aug.x + aug.y * aug.y + aug.z * aug.z + aug.w * aug.w), red);
    float mu2 = s2.x * invD;
    float rs2 = rsqrtf(s2.y * invD - mu2 * mu2 + 1e-5f);
    float4 gv2 = ((const float4*)tg)[tid], bv2 = ((const float4*)tb2)[tid];
    float4 tn;
    tn.x = (aug.x - mu2) * rs2 * gv2.x + bv2.x;
    tn.y = (aug.y - mu2) * rs2 * gv2.y + bv2.y;
    tn.z = (aug.z - mu2) * rs2 * gv2.z + bv2.z;
    tn.w = (aug.w - mu2) * rs2 * gv2.w + bv2.w;
    float2 s3 = bred2(make_float2(ptv.x + ptv.y + ptv.z + ptv.w,
                                  ptv.x * ptv.x + ptv.y * ptv.y + ptv.z * ptv.z + ptv.w * ptv.w), red);
    float mu3 = s3.x * invD;
    float rs3 = rsqrtf(s3.y * invD - mu3 * mu3 + 1e-5f);
    float4 gv3 = ((const float4*)pg)[tid], bv3 = ((const float4*)pb)[tid];
    float4 pn;
    pn.x = (ptv.x - mu3) * rs3 * gv3.x + bv3.x;
    pn.y = (ptv.y - mu3) * rs3 * gv3.y + bv3.y;
    pn.z = (ptv.z - mu3) * rs3 * gv3.z + bv3.z;
    pn.w = (ptv.w - mu3) * rs3 * gv3.w + bv3.w;
    {
        __nv_bfloat162* ct = (__nv_bfloat162*)(g_cat + (size_t)row * 2 * DD) + tid * 2;
        ct[0] = __floats2bfloat162_rn(tn.x, tn.y);
        ct[1] = __floats2bfloat162_rn(tn.z, tn.w);
        __nv_bfloat162* cp2 = (__nv_bfloat162*)(g_cat + (size_t)row * 2 * DD + DD) + tid * 2;
        cp2[0] = __floats2bfloat162_rn(pn.x, pn.y);
        cp2[1] = __floats2bfloat162_rn(pn.z, pn.w);
    }
    float2 s4 = bred2(make_float2(tn.x * pn.x + tn.y * pn.y + tn.z * pn.z + tn.w * pn.w,
                                  tn.x * tn.x + tn.y * tn.y + tn.z * tn.z + tn.w * tn.w), red);
    float2 s5 = bred2(make_float2(pn.x * pn.x + pn.y * pn.y + pn.z * pn.z + pn.w * pn.w, 0.f), red);
    if (tid == 0) {
        float cosv = s4.x / (fmaxf(sqrtf(s4.y), 1e-6f) * fmaxf(sqrtf(s5.x), 1e-6f));
        float ag = 0.5f * (1.0f + cosv);
        float z = (ag - 0.72f) / 0.2f;
        float focus = 0.2f + 0.8f * expf(-0.5f * z * z);
        g_gate[row] = ag * focus * stab[row];
    }
}

// ---------------- K7: causal pool + form bf16 GEMM inputs ----------------
__global__ void __launch_bounds__(256) k_pool() {
    int row = blockIdx.x;
    int b = row / SS, s = row % SS;
    int tid = threadIdx.x;
    size_t base = (size_t)row * DD;
    int s1 = s - 1; if (s1 < 0) s1 = 0;
    int s2 = s - 2; if (s2 < 0) s2 = 0;
    size_t b1 = ((size_t)b * SS + s1) * DD;
    size_t b2 = ((size_t)b * SS + s2) * DD;
    float4 x0 = ((const float4*)(g_shared + base))[tid];
    float4 x1 = ((const float4*)(g_shared + b1))[tid];
    float4 x2 = ((const float4*)(g_shared + b2))[tid];
    float4 pl;
    pl.x = (x0.x + x1.x + x2.x) / 3.0f;
    pl.y = (x0.y + x1.y + x2.y) / 3.0f;
    pl.z = (x0.z + x1.z + x2.z) / 3.0f;
    pl.w = (x0.w + x1.w + x2.w) / 3.0f;
    const __nv_bfloat162* ct = (const __nv_bfloat162*)(g_cat + (size_t)row * 2 * DD) + tid * 2;
    const __nv_bfloat162* cp2 = (const __nv_bfloat162*)(g_cat + (size_t)row * 2 * DD + DD) + tid * 2;
    float2 t01 = __bfloat1622float2(ct[0]);
    float2 t23 = __bfloat1622float2(ct[1]);
    float2 p01 = __bfloat1622float2(cp2[0]);
    float2 p23 = __bfloat1622float2(cp2[1]);
    __nv_bfloat162* o2 = (__nv_bfloat162*)(g_a2 + base) + tid * 2;
    o2[0] = __floats2bfloat162_rn(pl.x - t01.x, pl.y - t01.y);
    o2[1] = __floats2bfloat162_rn(pl.z - t23.x, pl.w - t23.y);
    __nv_bfloat162* o3 = (__nv_bfloat162*)(g_a3 + base) + tid * 2;
    o3[0] = __floats2bfloat162_rn(pl.x - p01.x, pl.y - p01.y);
    o3[1] = __floats2bfloat162_rn(pl.z - p23.x, pl.w - p23.y);
}

// ---------------- raw mma.sync bf16 GEMM ----------------
// block 128x128, BK=64, 3-stage cp.async, 128 threads (4 warps, warp tile 64x64).
// 2 CTAs/SM (96KB smem each; 128-thread CTAs tolerate up to 256 regs/thread).
// Per kk: 8 LDSM feed 32 MMAs (4:1) -> 33% less smem traffic per FLOP than 32x64 tiles.
// A smem: 128 rows x 128B (swizzle kc^=m&7);  B smem: 64 rows x 256B (swizzle nc^=k&15)
#define STG_BYTES 32768          // 16KB A + 16KB B per stage
#define GEMM_SMEM (3*STG_BYTES)  // 98304 -> 2 CTAs/SM

template<int MODE>
__global__ void __launch_bounds__(128) k_gemm(const __nv_bfloat16* __restrict__ A, int lda,
                                              const __nv_bfloat16* __restrict__ Bw,
                                              const float* __restrict__ bias,
                                              const float* __restrict__ wlast,
                                              const float* __restrict__ basept,
                                              const float* __restrict__ bscale,
                                              float* __restrict__ outp, int Ktot) {
    extern __shared__ char smem_raw[];
    const unsigned int sbase = (unsigned int)__cvta_generic_to_shared(smem_raw);
    const int tid = threadIdx.x, lane = tid & 31, wid = tid >> 5;
    const int wm = wid & 1, wn = wid >> 1;          // 2x2 warp grid, 64x64 tiles
    const int row0 = blockIdx.y * 128, col0 = blockIdx.x * 128;

    float acc[4][8][4];
#pragma unroll
    for (int i = 0; i < 4; i++)
#pragma unroll
        for (int j = 0; j < 8; j++)
#pragma unroll
            for (int q = 0; q < 4; q++) acc[i][j][q] = 0.0f;

    const int nIter = Ktot >> 6;

    auto load_stage = [&](int s, int kt) {
        unsigned int ab = sbase + s * STG_BYTES;
        unsigned int bb = ab + 16384;
#pragma unroll
        for (int p = 0; p < 8; p++) {
            int id = tid + 128 * p;
            int m = id >> 3, kc = id & 7;
            cp16s(ab + m * 128 + ((kc ^ (m & 7)) << 4),
                  A + (size_t)(row0 + m) * lda + kt * 64 + kc * 8);
            int k = id >> 4, nc = id & 15;
            cp16s(bb + k * 256 + ((nc ^ (k & 15)) << 4),
                  Bw + (size_t)(kt * 64 + k) * DD + col0 + nc * 8);
        }
        CP_COMMIT();
    };

    load_stage(0, 0);
    load_stage(1, 1);

    int st = 0;
    for (int it = 0; it < nIter; it++) {
        CP_WAIT1();
        __syncthreads();
        unsigned int ab = sbase + st * STG_BYTES;
        unsigned int bb = ab + 16384;
#pragma unroll
        for (int kk = 0; kk < 4; kk++) {
            unsigned int af[4][4], bf[8][2];
#pragma unroll
            for (int i = 0; i < 4; i++) {
                int r = wm * 64 + i * 16 + (lane & 15);
                int kc = kk * 2 + (lane >> 4);
                unsigned int addr = ab + r * 128 + ((kc ^ (r & 7)) << 4);
                asm volatile("ldmatrix.sync.aligned.m8n8.x4.shared.b16 {%0,%1,%2,%3}, [%4];"
                    : "=r"(af[i][0]), "=r"(af[i][1]), "=r"(af[i][2]), "=r"(af[i][3])
                    : "r"(addr));
            }
#pragma unroll
            for (int j = 0; j < 4; j++) {
                int r = kk * 16 + (lane & 7) + ((lane >> 3) & 1) * 8;
                int nc = wn * 8 + j * 2 + (lane >> 4);
                unsigned int addr = bb + r * 256 + ((nc ^ (r & 15)) << 4);
                asm volatile("ldmatrix.sync.aligned.m8n8.x4.trans.shared.b16 {%0,%1,%2,%3}, [%4];"
                    : "=r"(bf[2*j][0]), "=r"(bf[2*j][1]), "=r"(bf[2*j+1][0]), "=r"(bf[2*j+1][1])
                    : "r"(addr));
            }
#pragma unroll
            for (int i = 0; i < 4; i++)
#pragma unroll
                for (int j = 0; j < 8; j++)
                    asm volatile("mma.sync.aligned.m16n8k16.row.col.f32.bf16.bf16.f32 "
                        "{%0,%1,%2,%3}, {%4,%5,%6,%7}, {%8,%9}, {%0,%1,%2,%3};"
                        : "+f"(acc[i][j][0]), "+f"(acc[i][j][1]), "+f"(acc[i][j][2]), "+f"(acc[i][j][3])
                        : "r"(af[i][0]), "r"(af[i][1]), "r"(af[i][2]), "r"(af[i][3]),
                          "r"(bf[j][0]), "r"(bf[j][1]));
        }
        int nf = it + 2;
        if (nf < nIter) load_stage(nf - (nf / 3) * 3, nf);
        else CP_COMMIT();
        st++; if (st == 3) st = 0;
    }

    // epilogue straight from accumulator registers
    float blend = 0.0f;
    if (MODE != 1) blend = 0.35f / (1.0f + expf(-bscale[0]));
#pragma unroll
    for (int i = 0; i < 4; i++) {
        int rb = row0 + wm * 64 + i * 16 + (lane >> 2);
#pragma unroll
        for (int h = 0; h < 2; h++) {
            int r = rb + h * 8;
            float g = g_gate[r];
            float lb = blend * g;
#pragma unroll
            for (int j = 0; j < 8; j++) {
                int c = col0 + wn * 64 + j * 8 + (lane & 3) * 2;
                float v0 = acc[i][j][h * 2], v1 = acc[i][j][h * 2 + 1];
                if (MODE == 1) {
                    float2 bi = *(const float2*)(bias + c);
                    float2 wl = *(const float2*)(wlast + c);
                    float2 o = make_float2(v0 + bi.x + g * wl.x, v1 + bi.y + g * wl.y);
                    *(float2*)(g_shared + (size_t)r * DD + c) = o;
                } else {
                    const float* bp = (MODE == 2 ? g_tsaug : basept) + (size_t)r * DD + c;
                    float2 b2 = *(const float2*)bp;
                    float2 o = make_float2(b2.x + lb * v0, b2.y + lb * v1);
                    *(float2*)(outp + (size_t)r * DD + c) = o;
                }
            }
        }
    }
}

// ---------------- launch ----------------
extern "C" void kernel_launch(void* const* d_in, const int* in_sizes, int n_in,
                              void* d_out, int out_size) {
    const float* pt   = (const float*)d_in[0];
    const float* ts   = (const float*)d_in[1];
    const float* pos  = (const float*)d_in[2];
    const float* cent = (const float*)d_in[3];
    const float* stab = (const float*)d_in[4];
    const float* aw   = (const float*)d_in[5];
    const float* ab   = (const float*)d_in[6];
    const float* ta   = (const float*)d_in[7];
    const float* tb   = (const float*)d_in[8];
    const float* og   = (const float*)d_in[9];
    const float* ob   = (const float*)d_in[10];
    const float* tg   = (const float*)d_in[11];
    const float* tb2  = (const float*)d_in[12];
    const float* pg   = (const float*)d_in[13];
    const float* pb   = (const float*)d_in[14];
    const float* sW   = (const float*)d_in[15];
    const float* sb   = (const float*)d_in[16];
    const float* tuW  = (const float*)d_in[17];
    const float* puW  = (const float*)d_in[18];
    const float* bs   = (const float*)d_in[19];
    float* out = (float*)d_out;

    cudaFuncSetAttribute(k_gemm<1>, cudaFuncAttributeMaxDynamicSharedMemorySize, GEMM_SMEM);
    cudaFuncSetAttribute(k_gemm<2>, cudaFuncAttributeMaxDynamicSharedMemorySize, GEMM_SMEM);
    cudaFuncSetAttribute(k_gemm<3>, cudaFuncAttributeMaxDynamicSharedMemorySize, GEMM_SMEM);

    __nv_bfloat16 *w1p, *w2p, *w3p;
    cudaGetSymbolAddress((void**)&w1p, g_w1);
    cudaGetSymbolAddress((void**)&w2p, g_w2);
    cudaGetSymbolAddress((void**)&w3p, g_w3);
    __nv_bfloat16 *catp, *a2p, *a3p;
    cudaGetSymbolAddress((void**)&catp, g_cat);
    cudaGetSymbolAddress((void**)&a2p, g_a2);
    cudaGetSymbolAddress((void**)&a3p, g_a3);

    // weight conversions (tiny)
    k_cvt<<<(2048 * DD / 4 + 255) / 256, 256>>>(sW, w1p, 2048 * DD / 4);
    k_cvt<<<(DD * DD / 4 + 255) / 256, 256>>>(tuW, w2p, DD * DD / 4);
    k_cvt<<<(DD * DD / 4 + 255) / 256, 256>>>(puW, w3p, DD * DD / 4);

    k_scores<<<NROWS / 8, 256>>>(pt, aw, ab);
    k_top3<<<BB, 256>>>(pos);
    k_basis<<<BB * KA * MM, 128>>>(pt, cent, ta);
    k_mix<<<BB * KA, 128>>>(pos);
    k_translate<<<BB * KA * MM, 128>>>(tb);
    k_tcombine<<<BB * KA, 256>>>();
    k_rows<<<NROWS, 256>>>(ts, pt, pos, stab, og, ob, tg, tb2, pg, pb);

    dim3 gg(8, 256);
    k_gemm<1><<<gg, 128, GEMM_SMEM>>>(catp, 2 * DD, w1p, sb, sW + (size_t)2048 * DD,
                                      nullptr, nullptr, nullptr, 2048);
    k_pool<<<NROWS, 256>>>();
    k_gemm<2><<<gg, 128, GEMM_SMEM>>>(a2p, DD, w2p, nullptr, nullptr,
                                      nullptr, bs, out, 1024);
    k_gemm<3><<<gg, 128, GEMM_SMEM>>>(a3p, DD, w3p, nullptr, nullptr,
                                      pt, bs, out + (size_t)NROWS * DD, 1024);
}

// round 14
// speedup vs baseline: 1.3313x; 1.1536x over previous
#include <cuda_runtime.h>
#include <cuda_bf16.h>
#include <cstdint>

#define BB 8
#define SS 4096
#define DD 1024
#define MM 32
#define KA 3
#define RR 64
#define NROWS (BB*SS)

// ---------------- scratch (device globals; no allocations allowed) ----------------
__device__ float g_scores[NROWS];
__device__ int   g_aidx[BB*KA];
__device__ float g_apos[BB*KA];
__device__ float g_logits[BB*KA*MM];
__device__ float g_ua[BB*KA*MM*RR];
__device__ float g_w[BB*KA*MM];
__device__ float g_low[BB*KA*RR];
__device__ float g_Z[BB*KA];
__device__ float g_transp[BB*KA*MM*DD];
__device__ float g_trans[BB*KA*DD];
__device__ float g_tsaug[(size_t)NROWS*DD];
__device__ float g_gate[NROWS];
__device__ __align__(16) __nv_bfloat16 g_sharedh[(size_t)NROWS*DD];  // shared (bf16)
__device__ __align__(16) __nv_bfloat16 g_cat[(size_t)NROWS*2*DD];    // [tsn|ptn] bf16
__device__ __align__(16) __nv_bfloat16 g_a2[(size_t)NROWS*DD];
__device__ __align__(16) __nv_bfloat16 g_a3[(size_t)NROWS*DD];
__device__ __align__(16) __nv_bfloat16 g_w1[(size_t)2048*DD];        // shared_W[0:2048] bf16
__device__ __align__(16) __nv_bfloat16 g_w2[(size_t)DD*DD];          // ts_up_W bf16
__device__ __align__(16) __nv_bfloat16 g_w3[(size_t)DD*DD];          // pt_up_W bf16

// ---------------- cp.async helpers ----------------
__device__ __forceinline__ void cp16s(unsigned int dst_sh, const void* src) {
    asm volatile("cp.async.cg.shared.global [%0], [%1], 16;\n" :: "r"(dst_sh), "l"(src));
}
#define CP_COMMIT() asm volatile("cp.async.commit_group;\n" ::: "memory")
#define CP_WAIT1()  asm volatile("cp.async.wait_group 1;\n" ::: "memory")

// ---------------- weight fp32 -> bf16 ----------------
__global__ void __launch_bounds__(256) k_cvt(const float* __restrict__ src,
                                             __nv_bfloat16* __restrict__ dst, int n4) {
    int i = blockIdx.x * blockDim.x + threadIdx.x;
    if (i >= n4) return;
    float4 v = ((const float4*)src)[i];
    __nv_bfloat162* o = (__nv_bfloat162*)dst + i * 2;
    o[0] = __floats2bfloat162_rn(v.x, v.y);
    o[1] = __floats2bfloat162_rn(v.z, v.w);
}

// ---------------- K0: anchor scores ----------------
__global__ void __launch_bounds__(256) k_scores(const float* __restrict__ pt,
                                                const float* __restrict__ aw,
                                                const float* __restrict__ ab) {
    int gw = (blockIdx.x * blockDim.x + threadIdx.x) >> 5;
    int lane = threadIdx.x & 31;
    if (gw >= NROWS) return;
    const float4* p = (const float4*)(pt + (size_t)gw * DD);
    const float4* w = (const float4*)aw;
    float s = 0.f;
#pragma unroll
    for (int i = 0; i < 8; i++) {
        float4 a = p[lane + 32 * i];
        float4 b = w[lane + 32 * i];
        s += a.x * b.x + a.y * b.y + a.z * b.z + a.w * b.w;
    }
#pragma unroll
    for (int o = 16; o; o >>= 1) s += __shfl_down_sync(0xffffffffu, s, o);
    if (!lane) g_scores[gw] = s + ab[0];
}

// ---------------- K1: top-3 per batch ----------------
__global__ void k_top3(const float* __restrict__ pos) {
    __shared__ float sv[256];
    __shared__ int   si[256];
    __shared__ int   chosen[KA];
    int b = blockIdx.x, tid = threadIdx.x;
    const float* sc = g_scores + b * SS;
    for (int k = 0; k < KA; k++) {
        float bv = -3.4e38f; int bi = SS;
        for (int s = tid; s < SS; s += 256) {
            bool used = false;
            for (int j = 0; j < k; j++) used |= (chosen[j] == s);
            if (used) continue;
            float v = sc[s];
            if (v > bv || (v == bv && s < bi)) { bv = v; bi = s; }
        }
        sv[tid] = bv; si[tid] = bi;
        __syncthreads();
        for (int o = 128; o; o >>= 1) {
            if (tid < o) {
                if (sv[tid + o] > sv[tid] || (sv[tid + o] == sv[tid] && si[tid + o] < si[tid])) {
                    sv[tid] = sv[tid + o]; si[tid] = si[tid + o];
                }
            }
            __syncthreads();
        }
        if (tid == 0) {
            chosen[k] = si[0];
            g_aidx[b * KA + k] = si[0];
            g_apos[b * KA + k] = pos[si[0]];
        }
        __syncthreads();
    }
}

// ---------------- K2: per (b,k,m): cosine logit + u_a ----------------
__global__ void __launch_bounds__(128) k_basis(const float* __restrict__ pt,
                                               const float* __restrict__ cent,
                                               const float* __restrict__ ta) {
    __shared__ float av[DD];
    __shared__ float r1[128], r2[128], r3[128];
    int id = blockIdx.x;
    int m = id % MM, bk = id / MM;
    int b = bk / KA;
    int tid = threadIdx.x;
    const float* prow = pt + ((size_t)b * SS + g_aidx[bk]) * DD;
    const float* crow = cent + (size_t)m * DD;
    float pa = 0.f, pc = 0.f, pd = 0.f;
    for (int d = tid; d < DD; d += 128) {
        float a = prow[d], c = crow[d];
        av[d] = a; pa += a * a; pc += c * c; pd += a * c;
    }
    r1[tid] = pa; r2[tid] = pc; r3[tid] = pd;
    __syncthreads();
    for (int o = 64; o; o >>= 1) {
        if (tid < o) { r1[tid] += r1[tid + o]; r2[tid] += r2[tid + o]; r3[tid] += r3[tid + o]; }
        __syncthreads();
    }
    if (tid == 0) {
        float na = sqrtf(r1[0]), nc = sqrtf(r2[0]);
        g_logits[id] = r3[0] / (fmaxf(na, 1e-6f) * fmaxf(nc, 1e-6f));
    }
    __syncthreads();
    int r = tid & 63, h = tid >> 6;
    const float* tap = ta + (size_t)m * DD * RR + r;
    float u = 0.f;
    int d0 = h * 512;
#pragma unroll 8
    for (int d = d0; d < d0 + 512; d++) u += av[d] * tap[(size_t)d * RR];
    r1[tid] = u;
    __syncthreads();
    if (h == 0) g_ua[(size_t)id * RR + r] = r1[r] + r1[r + 64];
}

// ---------------- K3: per (b,k): softmax, low, spread normalizer ----------------
__global__ void __launch_bounds__(128) k_mix(const float* __restrict__ pos) {
    __shared__ float w[MM];
    __shared__ float red[128];
    int bk = blockIdx.x, tid = threadIdx.x;
    if (tid == 0) {
        float mx = -3.4e38f;
        for (int m = 0; m < MM; m++) mx = fmaxf(mx, g_logits[bk * MM + m]);
        float ssum = 0.f;
        for (int m = 0; m < MM; m++) { float e = expf(g_logits[bk * MM + m] - mx); w[m] = e; ssum += e; }
        float inv = 1.0f / ssum;
        for (int m = 0; m < MM; m++) w[m] *= inv;
    }
    __syncthreads();
    if (tid < MM) g_w[bk * MM + tid] = w[tid];
    if (tid < RR) {
        float lo = 0.f;
        for (int m = 0; m < MM; m++) lo += w[m] * g_ua[(size_t)(bk * MM + m) * RR + tid];
        g_low[bk * RR + tid] = lo;
    }
    float p = g_apos[bk];
    float z = 0.f;
    for (int s = tid; s < SS; s += 128) {
        float d = fabsf(pos[s] - p);
        if (d <= 8.0f) z += expf(-d * 0.125f);
    }
    red[tid] = z;
    __syncthreads();
    for (int o = 64; o; o >>= 1) { if (tid < o) red[tid] += red[tid + o]; __syncthreads(); }
    if (tid == 0) g_Z[bk] = red[0];
}

// ---------------- K4: per (b,k,m): partial translated ----------------
__global__ void __launch_bounds__(128) k_translate(const float* __restrict__ tb) {
    __shared__ float low[RR];
    __shared__ float wv;
    int id = blockIdx.x;
    int m = id % MM, bk = id / MM;
    int tid = threadIdx.x;
    if (tid < RR) low[tid] = g_low[bk * RR + tid];
    if (tid == 0) wv = g_w[bk * MM + m];
    __syncthreads();
    float wloc = wv;
    const float4* base = (const float4*)(tb + (size_t)m * DD * RR);
#pragma unroll
    for (int j = 0; j < 8; j++) {
        int d = tid + 128 * j;
        const float4* rp = base + (size_t)d * (RR / 4);
        float acc = 0.f;
#pragma unroll
        for (int i = 0; i < 16; i++) {
            float4 v = rp[i];
            acc += low[4 * i] * v.x + low[4 * i + 1] * v.y + low[4 * i + 2] * v.z + low[4 * i + 3] * v.w;
        }
        g_transp[(size_t)id * DD + d] = wloc * acc;
    }
}

__global__ void __launch_bounds__(256) k_tcombine() {
    int bk = blockIdx.x, tid = threadIdx.x;
    for (int d = tid; d < DD; d += 256) {
        float s = 0.f;
        for (int m = 0; m < MM; m++) s += g_transp[(size_t)(bk * MM + m) * DD + d];
        g_trans[bk * DD + d] = s;
    }
}

// ---------------- block reduce helper ----------------
__device__ __forceinline__ float2 bred2(float2 v, float* red) {
    int tid = threadIdx.x;
#pragma unroll
    for (int o = 16; o; o >>= 1) {
        v.x += __shfl_down_sync(0xffffffffu, v.x, o);
        v.y += __shfl_down_sync(0xffffffffu, v.y, o);
    }
    if ((tid & 31) == 0) { red[tid >> 5] = v.x; red[8 + (tid >> 5)] = v.y; }
    __syncthreads();
    if (tid == 0) {
        float a = 0.f, b = 0.f;
        for (int i = 0; i < 8; i++) { a += red[i]; b += red[8 + i]; }
        red[0] = a; red[8] = b;
    }
    __syncthreads();
    float2 r = make_float2(red[0], red[8]);
    __syncthreads();
    return r;
}

// ---------------- K5: fused row kernel (anchor update + 3 LNs + gate) ----------------
__global__ void __launch_bounds__(256) k_rows(
    const float* __restrict__ ts, const float* __restrict__ pt,
    const float* __restrict__ pos, const float* __restrict__ stab,
    const float* __restrict__ og, const float* __restrict__ ob,
    const float* __restrict__ tg, const float* __restrict__ tb2,
    const float* __restrict__ pg, const float* __restrict__ pb) {
    __shared__ float red[16];
    int row = blockIdx.x;
    int b = row / SS, s = row % SS;
    int tid = threadIdx.x;
    size_t base = (size_t)row * DD;
    float4 tsv = ((const float4*)(ts + base))[tid];
    float4 ptv = ((const float4*)(pt + base))[tid];
    float ps = pos[s];
    float4 upd = make_float4(0.f, 0.f, 0.f, 0.f);
#pragma unroll
    for (int k = 0; k < KA; k++) {
        int bk = b * KA + k;
        float dist = fabsf(ps - g_apos[bk]);
        if (dist <= 8.0f) {
            float c = expf(-dist * 0.125f) / g_Z[bk];
            float4 t = ((const float4*)(g_trans + (size_t)bk * DD))[tid];
            upd.x += c * t.x; upd.y += c * t.y; upd.z += c * t.z; upd.w += c * t.w;
        }
    }
    float4 x = make_float4(tsv.x + upd.x, tsv.y + upd.y, tsv.z + upd.z, tsv.w + upd.w);
    const float invD = 1.0f / DD;
    float2 s1 = bred2(make_float2(x.x + x.y + x.z + x.w,
                                  x.x * x.x + x.y * x.y + x.z * x.z + x.w * x.w), red);
    float mu = s1.x * invD;
    float var = s1.y * invD - mu * mu;
    float rs = rsqrtf(var + 1e-5f);
    float4 gv = ((const float4*)og)[tid], bv = ((const float4*)ob)[tid];
    float4 aug;
    aug.x = (x.x - mu) * rs * gv.x + bv.x;
    aug.y = (x.y - mu) * rs * gv.y + bv.y;
    aug.z = (x.z - mu) * rs * gv.z + bv.z;
    aug.w = (x.w - mu) * rs * gv.w + bv.w;
    ((float4*)(g_tsaug + base))[tid] = aug;
    float2 s2 = bred2(make_float2(aug.x + aug.y + aug.z + aug.w,
                                  aug.x * aug.x + aug.y * aug.y + aug.z * aug.z + aug.w * aug.w), red);
    float mu2 = s2.x * invD;
    float rs2 = rsqrtf(s2.y * invD - mu2 * mu2 + 1e-5f);
    float4 gv2 = ((const float4*)tg)[tid], bv2 = ((const float4*)tb2)[tid];
    float4 tn;
    tn.x = (aug.x - mu2) * rs2 * gv2.x + bv2.x;
    tn.y = (aug.y - mu2) * rs2 * gv2.y + bv2.y;
    tn.z = (aug.z - mu2) * rs2 * gv2.z + bv2.z;
    tn.w = (aug.w - mu2) * rs2 * gv2.w + bv2.w;
    float2 s3 = bred2(make_float2(ptv.x + ptv.y + ptv.z + ptv.w,
                                  ptv.x * ptv.x + ptv.y * ptv.y + ptv.z * ptv.z + ptv.w * ptv.w), red);
    float mu3 = s3.x * invD;
    float rs3 = rsqrtf(s3.y * invD - mu3 * mu3 + 1e-5f);
    float4 gv3 = ((const float4*)pg)[tid], bv3 = ((const float4*)pb)[tid];
    float4 pn;
    pn.x = (ptv.x - mu3) * rs3 * gv3.x + bv3.x;
    pn.y = (ptv.y - mu3) * rs3 * gv3.y + bv3.y;
    pn.z = (ptv.z - mu3) * rs3 * gv3.z + bv3.z;
    pn.w = (ptv.w - mu3) * rs3 * gv3.w + bv3.w;
    {
        __nv_bfloat162* ct = (__nv_bfloat162*)(g_cat + (size_t)row * 2 * DD) + tid * 2;
        ct[0] = __floats2bfloat162_rn(tn.x, tn.y);
        ct[1] = __floats2bfloat162_rn(tn.z, tn.w);
        __nv_bfloat162* cp2 = (__nv_bfloat162*)(g_cat + (size_t)row * 2 * DD + DD) + tid * 2;
        cp2[0] = __floats2bfloat162_rn(pn.x, pn.y);
        cp2[1] = __floats2bfloat162_rn(pn.z, pn.w);
    }
    float2 s4 = bred2(make_float2(tn.x * pn.x + tn.y * pn.y + tn.z * pn.z + tn.w * pn.w,
                                  tn.x * tn.x + tn.y * tn.y + tn.z * tn.z + tn.w * tn.w), red);
    float2 s5 = bred2(make_float2(pn.x * pn.x + pn.y * pn.y + pn.z * pn.z + pn.w * pn.w, 0.f), red);
    if (tid == 0) {
        float cosv = s4.x / (fmaxf(sqrtf(s4.y), 1e-6f) * fmaxf(sqrtf(s5.x), 1e-6f));
        float ag = 0.5f * (1.0f + cosv);
        float z = (ag - 0.72f) / 0.2f;
        float focus = 0.2f + 0.8f * expf(-0.5f * z * z);
        g_gate[row] = ag * focus * stab[row];
    }
}

// ---------------- K7: causal pool (bf16 shared) + form bf16 GEMM inputs ----------------
__global__ void __launch_bounds__(256) k_pool() {
    int row = blockIdx.x;
    int b = row / SS, s = row % SS;
    int tid = threadIdx.x;
    size_t base = (size_t)row * DD;
    int s1 = s - 1; if (s1 < 0) s1 = 0;
    int s2 = s - 2; if (s2 < 0) s2 = 0;
    size_t b1 = ((size_t)b * SS + s1) * DD;
    size_t b2 = ((size_t)b * SS + s2) * DD;
    const __nv_bfloat162* h0 = (const __nv_bfloat162*)(g_sharedh + base) + tid * 2;
    const __nv_bfloat162* h1 = (const __nv_bfloat162*)(g_sharedh + b1) + tid * 2;
    const __nv_bfloat162* h2 = (const __nv_bfloat162*)(g_sharedh + b2) + tid * 2;
    float2 a0 = __bfloat1622float2(h0[0]), a1 = __bfloat1622float2(h0[1]);
    float2 c0 = __bfloat1622float2(h1[0]), c1 = __bfloat1622float2(h1[1]);
    float2 e0 = __bfloat1622float2(h2[0]), e1 = __bfloat1622float2(h2[1]);
    float4 pl;
    pl.x = (a0.x + c0.x + e0.x) / 3.0f;
    pl.y = (a0.y + c0.y + e0.y) / 3.0f;
    pl.z = (a1.x + c1.x + e1.x) / 3.0f;
    pl.w = (a1.y + c1.y + e1.y) / 3.0f;
    const __nv_bfloat162* ct = (const __nv_bfloat162*)(g_cat + (size_t)row * 2 * DD) + tid * 2;
    const __nv_bfloat162* cp2 = (const __nv_bfloat162*)(g_cat + (size_t)row * 2 * DD + DD) + tid * 2;
    float2 t01 = __bfloat1622float2(ct[0]);
    float2 t23 = __bfloat1622float2(ct[1]);
    float2 p01 = __bfloat1622float2(cp2[0]);
    float2 p23 = __bfloat1622float2(cp2[1]);
    __nv_bfloat162* o2 = (__nv_bfloat162*)(g_a2 + base) + tid * 2;
    o2[0] = __floats2bfloat162_rn(pl.x - t01.x, pl.y - t01.y);
    o2[1] = __floats2bfloat162_rn(pl.z - t23.x, pl.w - t23.y);
    __nv_bfloat162* o3 = (__nv_bfloat162*)(g_a3 + base) + tid * 2;
    o3[0] = __floats2bfloat162_rn(pl.x - p01.x, pl.y - p01.y);
    o3[1] = __floats2bfloat162_rn(pl.z - p23.x, pl.w - p23.y);
}

// ---------------- raw mma.sync bf16 GEMM (R9 config, pinned occupancy) ----------------
// block 128x128, BK=64, 3-stage cp.async, 256 threads (8 warps, warp tile 32x64),
// __launch_bounds__(256,2) pins 2 CTAs/SM. Next-stage loads issued before MMAs.
// A smem: 128 rows x 128B (swizzle kc^=m&7);  B smem: 64 rows x 256B (swizzle nc^=k&15)
#define STG_BYTES 32768          // 16KB A + 16KB B per stage
#define GEMM_SMEM (3*STG_BYTES)  // 98304 -> 2 CTAs/SM

template<int MODE>
__global__ void __launch_bounds__(256, 2) k_gemm(const __nv_bfloat16* __restrict__ A, int lda,
                                                 const __nv_bfloat16* __restrict__ Bw,
                                                 const float* __restrict__ bias,
                                                 const float* __restrict__ wlast,
                                                 const float* __restrict__ basept,
                                                 const float* __restrict__ bscale,
                                                 float* __restrict__ outp, int Ktot) {
    extern __shared__ char smem_raw[];
    const unsigned int sbase = (unsigned int)__cvta_generic_to_shared(smem_raw);
    const int tid = threadIdx.x, lane = tid & 31, wid = tid >> 5;
    const int wm = wid & 3, wn = wid >> 2;
    const int row0 = blockIdx.y * 128, col0 = blockIdx.x * 128;

    float acc[2][8][4];
#pragma unroll
    for (int i = 0; i < 2; i++)
#pragma unroll
        for (int j = 0; j < 8; j++)
#pragma unroll
            for (int q = 0; q < 4; q++) acc[i][j][q] = 0.0f;

    const int nIter = Ktot >> 6;

    auto load_stage = [&](int s, int kt) {
        unsigned int ab = sbase + s * STG_BYTES;
        unsigned int bb = ab + 16384;
#pragma unroll
        for (int p = 0; p < 4; p++) {
            int id = tid + 256 * p;
            int m = id >> 3, kc = id & 7;
            cp16s(ab + m * 128 + ((kc ^ (m & 7)) << 4),
                  A + (size_t)(row0 + m) * lda + kt * 64 + kc * 8);
            int k = id >> 4, nc = id & 15;
            cp16s(bb + k * 256 + ((nc ^ (k & 15)) << 4),
                  Bw + (size_t)(kt * 64 + k) * DD + col0 + nc * 8);
        }
        CP_COMMIT();
    };

    load_stage(0, 0);
    load_stage(1, 1);

    int st = 0;
    for (int it = 0; it < nIter; it++) {
        CP_WAIT1();
        __syncthreads();
        // issue next stage's gmem loads first — a full tile of MMA work hides them
        int nf = it + 2;
        if (nf < nIter) load_stage(nf - (nf / 3) * 3, nf);
        else CP_COMMIT();
        unsigned int ab = sbase + st * STG_BYTES;
        unsigned int bb = ab + 16384;
#pragma unroll
        for (int kk = 0; kk < 4; kk++) {
            unsigned int af[2][4], bf[8][2];
#pragma unroll
            for (int i = 0; i < 2; i++) {
                int r = wm * 32 + i * 16 + (lane & 15);
                int kc = kk * 2 + (lane >> 4);
                unsigned int addr = ab + r * 128 + ((kc ^ (r & 7)) << 4);
                asm volatile("ldmatrix.sync.aligned.m8n8.x4.shared.b16 {%0,%1,%2,%3}, [%4];"
                    : "=r"(af[i][0]), "=r"(af[i][1]), "=r"(af[i][2]), "=r"(af[i][3])
                    : "r"(addr));
            }
#pragma unroll
            for (int j = 0; j < 4; j++) {
                int r = kk * 16 + (lane & 7) + ((lane >> 3) & 1) * 8;
                int nc = wn * 8 + j * 2 + (lane >> 4);
                unsigned int addr = bb + r * 256 + ((nc ^ (r & 15)) << 4);
                asm volatile("ldmatrix.sync.aligned.m8n8.x4.trans.shared.b16 {%0,%1,%2,%3}, [%4];"
                    : "=r"(bf[2*j][0]), "=r"(bf[2*j][1]), "=r"(bf[2*j+1][0]), "=r"(bf[2*j+1][1])
                    : "r"(addr));
            }
#pragma unroll
            for (int i = 0; i < 2; i++)
#pragma unroll
                for (int j = 0; j < 8; j++)
                    asm volatile("mma.sync.aligned.m16n8k16.row.col.f32.bf16.bf16.f32 "
                        "{%0,%1,%2,%3}, {%4,%5,%6,%7}, {%8,%9}, {%0,%1,%2,%3};"
                        : "+f"(acc[i][j][0]), "+f"(acc[i][j][1]), "+f"(acc[i][j][2]), "+f"(acc[i][j][3])
                        : "r"(af[i][0]), "r"(af[i][1]), "r"(af[i][2]), "r"(af[i][3]),
                          "r"(bf[j][0]), "r"(bf[j][1]));
        }
        st++; if (st == 3) st = 0;
    }

    // epilogue straight from accumulator registers
    float blend = 0.0f;
    if (MODE != 1) blend = 0.35f / (1.0f + expf(-bscale[0]));
#pragma unroll
    for (int i = 0; i < 2; i++) {
        int rb = row0 + wm * 32 + i * 16 + (lane >> 2);
#pragma unroll
        for (int h = 0; h < 2; h++) {
            int r = rb + h * 8;
            float g = g_gate[r];
            float lb = blend * g;
#pragma unroll
            for (int j = 0; j < 8; j++) {
                int c = col0 + wn * 64 + j * 8 + (lane & 3) * 2;
                float v0 = acc[i][j][h * 2], v1 = acc[i][j][h * 2 + 1];
                if (MODE == 1) {
                    float2 bi = *(const float2*)(bias + c);
                    float2 wl = *(const float2*)(wlast + c);
                    *(__nv_bfloat162*)(g_sharedh + (size_t)r * DD + c) =
                        __floats2bfloat162_rn(v0 + bi.x + g * wl.x, v1 + bi.y + g * wl.y);
                } else {
                    const float* bp = (MODE == 2 ? g_tsaug : basept) + (size_t)r * DD + c;
                    float2 b2 = *(const float2*)bp;
                    float2 o = make_float2(b2.x + lb * v0, b2.y + lb * v1);
                    *(float2*)(outp + (size_t)r * DD + c) = o;
                }
            }
        }
    }
}

// ---------------- launch ----------------
extern "C" void kernel_launch(void* const* d_in, const int* in_sizes, int n_in,
                              void* d_out, int out_size) {
    const float* pt   = (const float*)d_in[0];
    const float* ts   = (const float*)d_in[1];
    const float* pos  = (const float*)d_in[2];
    const float* cent = (const float*)d_in[3];
    const float* stab = (const float*)d_in[4];
    const float* aw   = (const float*)d_in[5];
    const float* ab   = (const float*)d_in[6];
    const float* ta   = (const float*)d_in[7];
    const float* tb   = (const float*)d_in[8];
    const float* og   = (const float*)d_in[9];
    const float* ob   = (const float*)d_in[10];
    const float* tg   = (const float*)d_in[11];
    const float* tb2  = (const float*)d_in[12];
    const float* pg   = (const float*)d_in[13];
    const float* pb   = (const float*)d_in[14];
    const float* sW   = (const float*)d_in[15];
    const float* sb   = (const float*)d_in[16];
    const float* tuW  = (const float*)d_in[17];
    const float* puW  = (const float*)d_in[18];
    const float* bs   = (const float*)d_in[19];
    float* out = (float*)d_out;

    cudaFuncSetAttribute(k_gemm<1>, cudaFuncAttributeMaxDynamicSharedMemorySize, GEMM_SMEM);
    cudaFuncSetAttribute(k_gemm<2>, cudaFuncAttributeMaxDynamicSharedMemorySize, GEMM_SMEM);
    cudaFuncSetAttribute(k_gemm<3>, cudaFuncAttributeMaxDynamicSharedMemorySize, GEMM_SMEM);

    __nv_bfloat16 *w1p, *w2p, *w3p, *catp, *a2p, *a3p;
    cudaGetSymbolAddress((void**)&w1p, g_w1);
    cudaGetSymbolAddress((void**)&w2p, g_w2);
    cudaGetSymbolAddress((void**)&w3p, g_w3);
    cudaGetSymbolAddress((void**)&catp, g_cat);
    cudaGetSymbolAddress((void**)&a2p, g_a2);
    cudaGetSymbolAddress((void**)&a3p, g_a3);

    // weight conversions (tiny)
    k_cvt<<<(2048 * DD / 4 + 255) / 256, 256>>>(sW, w1p, 2048 * DD / 4);
    k_cvt<<<(DD * DD / 4 + 255) / 256, 256>>>(tuW, w2p, DD * DD / 4);
    k_cvt<<<(DD * DD / 4 + 255) / 256, 256>>>(puW, w3p, DD * DD / 4);

    k_scores<<<NROWS / 8, 256>>>(pt, aw, ab);
    k_top3<<<BB, 256>>>(pos);
    k_basis<<<BB * KA * MM, 128>>>(pt, cent, ta);
    k_mix<<<BB * KA, 128>>>(pos);
    k_translate<<<BB * KA * MM, 128>>>(tb);
    k_tcombine<<<BB * KA, 256>>>();
    k_rows<<<NROWS, 256>>>(ts, pt, pos, stab, og, ob, tg, tb2, pg, pb);

    dim3 gg(8, 256);
    k_gemm<1><<<gg, 256, GEMM_SMEM>>>(catp, 2 * DD, w1p, sb, sW + (size_t)2048 * DD,
                                      nullptr, nullptr, nullptr, 2048);
    k_pool<<<NROWS, 256>>>();
    k_gemm<2><<<gg, 256, GEMM_SMEM>>>(a2p, DD, w2p, nullptr, nullptr,
                                      nullptr, bs, out, 1024);
    k_gemm<3><<<gg, 256, GEMM_SMEM>>>(a3p, DD, w3p, nullptr, nullptr,
                                      pt, bs, out + (size_t)NROWS * DD, 1024);
}

// round 15
// speedup vs baseline: 1.3831x; 1.0389x over previous
#include <cuda_runtime.h>
#include <cuda_bf16.h>
#include <cstdint>

#define BB 8
#define SS 4096
#define DD 1024
#define MM 32
#define KA 3
#define RR 64
#define NROWS (BB*SS)

// ---------------- scratch (device globals; no allocations allowed) ----------------
__device__ float g_scores[NROWS];
__device__ int   g_aidx[BB*KA];
__device__ float g_apos[BB*KA];
__device__ float g_logits[BB*KA*MM];
__device__ float g_ua[BB*KA*MM*RR];
__device__ float g_w[BB*KA*MM];
__device__ float g_low[BB*KA*RR];
__device__ float g_Z[BB*KA];
__device__ float g_transp[BB*KA*MM*DD];
__device__ float g_trans[BB*KA*DD];
__device__ float g_tsaug[(size_t)NROWS*DD];
__device__ float g_gate[NROWS];
__device__ __align__(16) __nv_bfloat16 g_sharedh[(size_t)NROWS*DD];  // shared (bf16)
__device__ __align__(16) __nv_bfloat16 g_cat[(size_t)NROWS*2*DD];    // [tsn|ptn] bf16
__device__ __align__(16) __nv_bfloat16 g_a2[(size_t)NROWS*DD];
__device__ __align__(16) __nv_bfloat16 g_a3[(size_t)NROWS*DD];
__device__ __align__(16) __nv_bfloat16 g_w1[(size_t)2048*DD];        // shared_W[0:2048] bf16
__device__ __align__(16) __nv_bfloat16 g_w2[(size_t)DD*DD];          // ts_up_W bf16
__device__ __align__(16) __nv_bfloat16 g_w3[(size_t)DD*DD];          // pt_up_W bf16

// ---------------- cp.async helpers ----------------
__device__ __forceinline__ void cp16s(unsigned int dst_sh, const void* src) {
    asm volatile("cp.async.cg.shared.global [%0], [%1], 16;\n" :: "r"(dst_sh), "l"(src));
}
#define CP_COMMIT() asm volatile("cp.async.commit_group;\n" ::: "memory")
#define CP_WAIT1()  asm volatile("cp.async.wait_group 1;\n" ::: "memory")

// ---------------- all weight fp32 -> bf16 in ONE launch ----------------
// blocks [0, G1): sW -> g_w1 ; [G1, G1+G2): tuW -> g_w2 ; [G1+G2, G1+2*G2): puW -> g_w3
#define CVT_G1 (2048*DD/4/256)   // 2048 blocks
#define CVT_G2 (DD*DD/4/256)     // 1024 blocks
__global__ void __launch_bounds__(256) k_cvtall(const float* __restrict__ sW,
                                                const float* __restrict__ tuW,
                                                const float* __restrict__ puW) {
    int blk = blockIdx.x;
    const float* src;
    __nv_bfloat16* dst;
    int i;
    if (blk < CVT_G1)               { src = sW;  dst = g_w1; i = blk * 256 + threadIdx.x; }
    else if (blk < CVT_G1 + CVT_G2) { src = tuW; dst = g_w2; i = (blk - CVT_G1) * 256 + threadIdx.x; }
    else                            { src = puW; dst = g_w3; i = (blk - CVT_G1 - CVT_G2) * 256 + threadIdx.x; }
    float4 v = ((const float4*)src)[i];
    __nv_bfloat162* o = (__nv_bfloat162*)dst + (size_t)i * 2;
    o[0] = __floats2bfloat162_rn(v.x, v.y);
    o[1] = __floats2bfloat162_rn(v.z, v.w);
}

// ---------------- K0: anchor scores ----------------
__global__ void __launch_bounds__(256) k_scores(const float* __restrict__ pt,
                                                const float* __restrict__ aw,
                                                const float* __restrict__ ab) {
    int gw = (blockIdx.x * blockDim.x + threadIdx.x) >> 5;
    int lane = threadIdx.x & 31;
    if (gw >= NROWS) return;
    const float4* p = (const float4*)(pt + (size_t)gw * DD);
    const float4* w = (const float4*)aw;
    float s = 0.f;
#pragma unroll
    for (int i = 0; i < 8; i++) {
        float4 a = p[lane + 32 * i];
        float4 b = w[lane + 32 * i];
        s += a.x * b.x + a.y * b.y + a.z * b.z + a.w * b.w;
    }
#pragma unroll
    for (int o = 16; o; o >>= 1) s += __shfl_down_sync(0xffffffffu, s, o);
    if (!lane) g_scores[gw] = s + ab[0];
}

// ---------------- K1: top-3 per batch ----------------
__global__ void k_top3(const float* __restrict__ pos) {
    __shared__ float sv[256];
    __shared__ int   si[256];
    __shared__ int   chosen[KA];
    int b = blockIdx.x, tid = threadIdx.x;
    const float* sc = g_scores + b * SS;
    for (int k = 0; k < KA; k++) {
        float bv = -3.4e38f; int bi = SS;
        for (int s = tid; s < SS; s += 256) {
            bool used = false;
            for (int j = 0; j < k; j++) used |= (chosen[j] == s);
            if (used) continue;
            float v = sc[s];
            if (v > bv || (v == bv && s < bi)) { bv = v; bi = s; }
        }
        sv[tid] = bv; si[tid] = bi;
        __syncthreads();
        for (int o = 128; o; o >>= 1) {
            if (tid < o) {
                if (sv[tid + o] > sv[tid] || (sv[tid + o] == sv[tid] && si[tid + o] < si[tid])) {
                    sv[tid] = sv[tid + o]; si[tid] = si[tid + o];
                }
            }
            __syncthreads();
        }
        if (tid == 0) {
            chosen[k] = si[0];
            g_aidx[b * KA + k] = si[0];
            g_apos[b * KA + k] = pos[si[0]];
        }
        __syncthreads();
    }
}

// ---------------- K2: per (b,k,m): cosine logit + u_a ----------------
__global__ void __launch_bounds__(128) k_basis(const float* __restrict__ pt,
                                               const float* __restrict__ cent,
                                               const float* __restrict__ ta) {
    __shared__ float av[DD];
    __shared__ float r1[128], r2[128], r3[128];
    int id = blockIdx.x;
    int m = id % MM, bk = id / MM;
    int b = bk / KA;
    int tid = threadIdx.x;
    const float* prow = pt + ((size_t)b * SS + g_aidx[bk]) * DD;
    const float* crow = cent + (size_t)m * DD;
    float pa = 0.f, pc = 0.f, pd = 0.f;
    for (int d = tid; d < DD; d += 128) {
        float a = prow[d], c = crow[d];
        av[d] = a; pa += a * a; pc += c * c; pd += a * c;
    }
    r1[tid] = pa; r2[tid] = pc; r3[tid] = pd;
    __syncthreads();
    for (int o = 64; o; o >>= 1) {
        if (tid < o) { r1[tid] += r1[tid + o]; r2[tid] += r2[tid + o]; r3[tid] += r3[tid + o]; }
        __syncthreads();
    }
    if (tid == 0) {
        float na = sqrtf(r1[0]), nc = sqrtf(r2[0]);
        g_logits[id] = r3[0] / (fmaxf(na, 1e-6f) * fmaxf(nc, 1e-6f));
    }
    __syncthreads();
    int r = tid & 63, h = tid >> 6;
    const float* tap = ta + (size_t)m * DD * RR + r;
    float u = 0.f;
    int d0 = h * 512;
#pragma unroll 8
    for (int d = d0; d < d0 + 512; d++) u += av[d] * tap[(size_t)d * RR];
    r1[tid] = u;
    __syncthreads();
    if (h == 0) g_ua[(size_t)id * RR + r] = r1[r] + r1[r + 64];
}

// ---------------- K3: per (b,k): softmax, low, spread normalizer ----------------
__global__ void __launch_bounds__(128) k_mix(const float* __restrict__ pos) {
    __shared__ float w[MM];
    __shared__ float red[128];
    int bk = blockIdx.x, tid = threadIdx.x;
    if (tid == 0) {
        float mx = -3.4e38f;
        for (int m = 0; m < MM; m++) mx = fmaxf(mx, g_logits[bk * MM + m]);
        float ssum = 0.f;
        for (int m = 0; m < MM; m++) { float e = expf(g_logits[bk * MM + m] - mx); w[m] = e; ssum += e; }
        float inv = 1.0f / ssum;
        for (int m = 0; m < MM; m++) w[m] *= inv;
    }
    __syncthreads();
    if (tid < MM) g_w[bk * MM + tid] = w[tid];
    if (tid < RR) {
        float lo = 0.f;
        for (int m = 0; m < MM; m++) lo += w[m] * g_ua[(size_t)(bk * MM + m) * RR + tid];
        g_low[bk * RR + tid] = lo;
    }
    float p = g_apos[bk];
    float z = 0.f;
    for (int s = tid; s < SS; s += 128) {
        float d = fabsf(pos[s] - p);
        if (d <= 8.0f) z += expf(-d * 0.125f);
    }
    red[tid] = z;
    __syncthreads();
    for (int o = 64; o; o >>= 1) { if (tid < o) red[tid] += red[tid + o]; __syncthreads(); }
    if (tid == 0) g_Z[bk] = red[0];
}

// ---------------- K4: per (b,k,m): partial translated ----------------
__global__ void __launch_bounds__(128) k_translate(const float* __restrict__ tb) {
    __shared__ float low[RR];
    __shared__ float wv;
    int id = blockIdx.x;
    int m = id % MM, bk = id / MM;
    int tid = threadIdx.x;
    if (tid < RR) low[tid] = g_low[bk * RR + tid];
    if (tid == 0) wv = g_w[bk * MM + m];
    __syncthreads();
    float wloc = wv;
    const float4* base = (const float4*)(tb + (size_t)m * DD * RR);
#pragma unroll
    for (int j = 0; j < 8; j++) {
        int d = tid + 128 * j;
        const float4* rp = base + (size_t)d * (RR / 4);
        float acc = 0.f;
#pragma unroll
        for (int i = 0; i < 16; i++) {
            float4 v = rp[i];
            acc += low[4 * i] * v.x + low[4 * i + 1] * v.y + low[4 * i + 2] * v.z + low[4 * i + 3] * v.w;
        }
        g_transp[(size_t)id * DD + d] = wloc * acc;
    }
}

__global__ void __launch_bounds__(256) k_tcombine() {
    int bk = blockIdx.x, tid = threadIdx.x;
    for (int d = tid; d < DD; d += 256) {
        float s = 0.f;
        for (int m = 0; m < MM; m++) s += g_transp[(size_t)(bk * MM + m) * DD + d];
        g_trans[bk * DD + d] = s;
    }
}

// ---------------- block reduce helper ----------------
__device__ __forceinline__ float2 bred2(float2 v, float* red) {
    int tid = threadIdx.x;
#pragma unroll
    for (int o = 16; o; o >>= 1) {
        v.x += __shfl_down_sync(0xffffffffu, v.x, o);
        v.y += __shfl_down_sync(0xffffffffu, v.y, o);
    }
    if ((tid & 31) == 0) { red[tid >> 5] = v.x; red[8 + (tid >> 5)] = v.y; }
    __syncthreads();
    if (tid == 0) {
        float a = 0.f, b = 0.f;
        for (int i = 0; i < 8; i++) { a += red[i]; b += red[8 + i]; }
        red[0] = a; red[8] = b;
    }
    __syncthreads();
    float2 r = make_float2(red[0], red[8]);
    __syncthreads();
    return r;
}

// ---------------- K5: fused row kernel (anchor update + 3 LNs + gate) ----------------
__global__ void __launch_bounds__(256) k_rows(
    const float* __restrict__ ts, const float* __restrict__ pt,
    const float* __restrict__ pos, const float* __restrict__ stab,
    const float* __restrict__ og, const float* __restrict__ ob,
    const float* __restrict__ tg, const float* __restrict__ tb2,
    const float* __restrict__ pg, const float* __restrict__ pb) {
    __shared__ float red[16];
    int row = blockIdx.x;
    int b = row / SS, s = row % SS;
    int tid = threadIdx.x;
    size_t base = (size_t)row * DD;
    float4 tsv = ((const float4*)(ts + base))[tid];
    float4 ptv = ((const float4*)(pt + base))[tid];
    float ps = pos[s];
    float4 upd = make_float4(0.f, 0.f, 0.f, 0.f);
#pragma unroll
    for (int k = 0; k < KA; k++) {
        int bk = b * KA + k;
        float dist = fabsf(ps - g_apos[bk]);
        if (dist <= 8.0f) {
            float c = expf(-dist * 0.125f) / g_Z[bk];
            float4 t = ((const float4*)(g_trans + (size_t)bk * DD))[tid];
            upd.x += c * t.x; upd.y += c * t.y; upd.z += c * t.z; upd.w += c * t.w;
        }
    }
    float4 x = make_float4(tsv.x + upd.x, tsv.y + upd.y, tsv.z + upd.z, tsv.w + upd.w);
    const float invD = 1.0f / DD;
    float2 s1 = bred2(make_float2(x.x + x.y + x.z + x.w,
                                  x.x * x.x + x.y * x.y + x.z * x.z + x.w * x.w), red);
    float mu = s1.x * invD;
    float var = s1.y * invD - mu * mu;
    float rs = rsqrtf(var + 1e-5f);
    float4 gv = ((const float4*)og)[tid], bv = ((const float4*)ob)[tid];
    float4 aug;
    aug.x = (x.x - mu) * rs * gv.x + bv.x;
    aug.y = (x.y - mu) * rs * gv.y + bv.y;
    aug.z = (x.z - mu) * rs * gv.z + bv.z;
    aug.w = (x.w - mu) * rs * gv.w + bv.w;
    ((float4*)(g_tsaug + base))[tid] = aug;
    float2 s2 = bred2(make_float2(aug.x + aug.y + aug.z + aug.w,
                                  aug.x * aug.x + aug.y * aug.y + aug.z * aug.z + aug.w * aug.w), red);
    float mu2 = s2.x * invD;
    float rs2 = rsqrtf(s2.y * invD - mu2 * mu2 + 1e-5f);
    float4 gv2 = ((const float4*)tg)[tid], bv2 = ((const float4*)tb2)[tid];
    float4 tn;
    tn.x = (aug.x - mu2) * rs2 * gv2.x + bv2.x;
    tn.y = (aug.y - mu2) * rs2 * gv2.y + bv2.y;
    tn.z = (aug.z - mu2) * rs2 * gv2.z + bv2.z;
    tn.w = (aug.w - mu2) * rs2 * gv2.w + bv2.w;
    float2 s3 = bred2(make_float2(ptv.x + ptv.y + ptv.z + ptv.w,
                                  ptv.x * ptv.x + ptv.y * ptv.y + ptv.z * ptv.z + ptv.w * ptv.w), red);
    float mu3 = s3.x * invD;
    float rs3 = rsqrtf(s3.y * invD - mu3 * mu3 + 1e-5f);
    float4 gv3 = ((const float4*)pg)[tid], bv3 = ((const float4*)pb)[tid];
    float4 pn;
    pn.x = (ptv.x - mu3) * rs3 * gv3.x + bv3.x;
    pn.y = (ptv.y - mu3) * rs3 * gv3.y + bv3.y;
    pn.z = (ptv.z - mu3) * rs3 * gv3.z + bv3.z;
    pn.w = (ptv.w - mu3) * rs3 * gv3.w + bv3.w;
    {
        __nv_bfloat162* ct = (__nv_bfloat162*)(g_cat + (size_t)row * 2 * DD) + tid * 2;
        ct[0] = __floats2bfloat162_rn(tn.x, tn.y);
        ct[1] = __floats2bfloat162_rn(tn.z, tn.w);
        __nv_bfloat162* cp2 = (__nv_bfloat162*)(g_cat + (size_t)row * 2 * DD + DD) + tid * 2;
        cp2[0] = __floats2bfloat162_rn(pn.x, pn.y);
        cp2[1] = __floats2bfloat162_rn(pn.z, pn.w);
    }
    float2 s4 = bred2(make_float2(tn.x * pn.x + tn.y * pn.y + tn.z * pn.z + tn.w * pn.w,
                                  tn.x * tn.x + tn.y * tn.y + tn.z * tn.z + tn.w * tn.w), red);
    float2 s5 = bred2(make_float2(pn.x * pn.x + pn.y * pn.y + pn.z * pn.z + pn.w * pn.w, 0.f), red);
    if (tid == 0) {
        float cosv = s4.x / (fmaxf(sqrtf(s4.y), 1e-6f) * fmaxf(sqrtf(s5.x), 1e-6f));
        float ag = 0.5f * (1.0f + cosv);
        float z = (ag - 0.72f) / 0.2f;
        float focus = 0.2f + 0.8f * expf(-0.5f * z * z);
        g_gate[row] = ag * focus * stab[row];
    }
}

// ---------------- K7: causal pool (bf16 shared) + form bf16 GEMM inputs ----------------
__global__ void __launch_bounds__(256) k_pool() {
    int row = blockIdx.x;
    int b = row / SS, s = row % SS;
    int tid = threadIdx.x;
    size_t base = (size_t)row * DD;
    int s1 = s - 1; if (s1 < 0) s1 = 0;
    int s2 = s - 2; if (s2 < 0) s2 = 0;
    size_t b1 = ((size_t)b * SS + s1) * DD;
    size_t b2 = ((size_t)b * SS + s2) * DD;
    const __nv_bfloat162* h0 = (const __nv_bfloat162*)(g_sharedh + base) + tid * 2;
    const __nv_bfloat162* h1 = (const __nv_bfloat162*)(g_sharedh + b1) + tid * 2;
    const __nv_bfloat162* h2 = (const __nv_bfloat162*)(g_sharedh + b2) + tid * 2;
    float2 a0 = __bfloat1622float2(h0[0]), a1 = __bfloat1622float2(h0[1]);
    float2 c0 = __bfloat1622float2(h1[0]), c1 = __bfloat1622float2(h1[1]);
    float2 e0 = __bfloat1622float2(h2[0]), e1 = __bfloat1622float2(h2[1]);
    float4 pl;
    pl.x = (a0.x + c0.x + e0.x) / 3.0f;
    pl.y = (a0.y + c0.y + e0.y) / 3.0f;
    pl.z = (a1.x + c1.x + e1.x) / 3.0f;
    pl.w = (a1.y + c1.y + e1.y) / 3.0f;
    const __nv_bfloat162* ct = (const __nv_bfloat162*)(g_cat + (size_t)row * 2 * DD) + tid * 2;
    const __nv_bfloat162* cp2 = (const __nv_bfloat162*)(g_cat + (size_t)row * 2 * DD + DD) + tid * 2;
    float2 t01 = __bfloat1622float2(ct[0]);
    float2 t23 = __bfloat1622float2(ct[1]);
    float2 p01 = __bfloat1622float2(cp2[0]);
    float2 p23 = __bfloat1622float2(cp2[1]);
    __nv_bfloat162* o2 = (__nv_bfloat162*)(g_a2 + base) + tid * 2;
    o2[0] = __floats2bfloat162_rn(pl.x - t01.x, pl.y - t01.y);
    o2[1] = __floats2bfloat162_rn(pl.z - t23.x, pl.w - t23.y);
    __nv_bfloat162* o3 = (__nv_bfloat162*)(g_a3 + base) + tid * 2;
    o3[0] = __floats2bfloat162_rn(pl.x - p01.x, pl.y - p01.y);
    o3[1] = __floats2bfloat162_rn(pl.z - p23.x, pl.w - p23.y);
}

// ---------------- raw mma.sync bf16 GEMM core (R14 config) ----------------
// block 128x128, BK=64, 3-stage cp.async, 256 threads (8 warps, warp tile 32x64),
// __launch_bounds__(256,2) pins 2 CTAs/SM. Next-stage loads issued before MMAs.
#define STG_BYTES 32768          // 16KB A + 16KB B per stage
#define GEMM_SMEM (3*STG_BYTES)  // 98304 -> 2 CTAs/SM

__device__ __forceinline__ void gemm_core(const __nv_bfloat16* __restrict__ A, int lda,
                                          const __nv_bfloat16* __restrict__ Bw,
                                          int row0, int col0, int Ktot,
                                          unsigned int sbase, float (&acc)[2][8][4]) {
    const int tid = threadIdx.x, lane = tid & 31, wid = tid >> 5;
    const int wm = wid & 3, wn = wid >> 2;

    auto load_stage = [&](int s, int kt) {
        unsigned int ab = sbase + s * STG_BYTES;
        unsigned int bb = ab + 16384;
#pragma unroll
        for (int p = 0; p < 4; p++) {
            int id = tid + 256 * p;
            int m = id >> 3, kc = id & 7;
            cp16s(ab + m * 128 + ((kc ^ (m & 7)) << 4),
                  A + (size_t)(row0 + m) * lda + kt * 64 + kc * 8);
            int k = id >> 4, nc = id & 15;
            cp16s(bb + k * 256 + ((nc ^ (k & 15)) << 4),
                  Bw + (size_t)(kt * 64 + k) * DD + col0 + nc * 8);
        }
        CP_COMMIT();
    };

    const int nIter = Ktot >> 6;
    load_stage(0, 0);
    load_stage(1, 1);

    int st = 0;
    for (int it = 0; it < nIter; it++) {
        CP_WAIT1();
        __syncthreads();
        int nf = it + 2;
        if (nf < nIter) load_stage(nf - (nf / 3) * 3, nf);
        else CP_COMMIT();
        unsigned int ab = sbase + st * STG_BYTES;
        unsigned int bb = ab + 16384;
#pragma unroll
        for (int kk = 0; kk < 4; kk++) {
            unsigned int af[2][4], bf[8][2];
#pragma unroll
            for (int j = 0; j < 4; j++) {
                int r = kk * 16 + (lane & 7) + ((lane >> 3) & 1) * 8;
                int nc = wn * 8 + j * 2 + (lane >> 4);
                unsigned int addr = bb + r * 256 + ((nc ^ (r & 15)) << 4);
                asm volatile("ldmatrix.sync.aligned.m8n8.x4.trans.shared.b16 {%0,%1,%2,%3}, [%4];"
                    : "=r"(bf[2*j][0]), "=r"(bf[2*j][1]), "=r"(bf[2*j+1][0]), "=r"(bf[2*j+1][1])
                    : "r"(addr));
            }
#pragma unroll
            for (int i = 0; i < 2; i++) {
                int r = wm * 32 + i * 16 + (lane & 15);
                int kc = kk * 2 + (lane >> 4);
                unsigned int addr = ab + r * 128 + ((kc ^ (r & 7)) << 4);
                asm volatile("ldmatrix.sync.aligned.m8n8.x4.shared.b16 {%0,%1,%2,%3}, [%4];"
                    : "=r"(af[i][0]), "=r"(af[i][1]), "=r"(af[i][2]), "=r"(af[i][3])
                    : "r"(addr));
            }
#pragma unroll
            for (int i = 0; i < 2; i++)
#pragma unroll
                for (int j = 0; j < 8; j++)
                    asm volatile("mma.sync.aligned.m16n8k16.row.col.f32.bf16.bf16.f32 "
                        "{%0,%1,%2,%3}, {%4,%5,%6,%7}, {%8,%9}, {%0,%1,%2,%3};"
                        : "+f"(acc[i][j][0]), "+f"(acc[i][j][1]), "+f"(acc[i][j][2]), "+f"(acc[i][j][3])
                        : "r"(af[i][0]), "r"(af[i][1]), "r"(af[i][2]), "r"(af[i][3]),
                          "r"(bf[j][0]), "r"(bf[j][1]));
        }
        st++; if (st == 3) st = 0;
    }
}

// MODE1: shared = [tsn|ptn] @ W1 + bias + gate*wlast  (K=2048), bf16 out to g_sharedh
__global__ void __launch_bounds__(256, 2) k_gemm1(const float* __restrict__ bias,
                                                  const float* __restrict__ wlast) {
    extern __shared__ char smem_raw[];
    const unsigned int sbase = (unsigned int)__cvta_generic_to_shared(smem_raw);
    const int tid = threadIdx.x, lane = tid & 31, wid = tid >> 5;
    const int wm = wid & 3, wn = wid >> 2;
    const int row0 = blockIdx.y * 128, col0 = blockIdx.x * 128;

    float acc[2][8][4];
#pragma unroll
    for (int i = 0; i < 2; i++)
#pragma unroll
        for (int j = 0; j < 8; j++)
#pragma unroll
            for (int q = 0; q < 4; q++) acc[i][j][q] = 0.0f;

    gemm_core(g_cat, 2 * DD, g_w1, row0, col0, 2048, sbase, acc);

#pragma unroll
    for (int i = 0; i < 2; i++) {
        int rb = row0 + wm * 32 + i * 16 + (lane >> 2);
#pragma unroll
        for (int h = 0; h < 2; h++) {
            int r = rb + h * 8;
            float g = g_gate[r];
#pragma unroll
            for (int j = 0; j < 8; j++) {
                int c = col0 + wn * 64 + j * 8 + (lane & 3) * 2;
                float v0 = acc[i][j][h * 2], v1 = acc[i][j][h * 2 + 1];
                float2 bi = *(const float2*)(bias + c);
                float2 wl = *(const float2*)(wlast + c);
                *(__nv_bfloat162*)(g_sharedh + (size_t)r * DD + c) =
                    __floats2bfloat162_rn(v0 + bi.x + g * wl.x, v1 + bi.y + g * wl.y);
            }
        }
    }
}

// MODE2+3 merged (blockIdx.z): z=0: ts_out = tsaug + lb*(a2@w2); z=1: pt_out = pt + lb*(a3@w3)
__global__ void __launch_bounds__(256, 2) k_gemm23(const float* __restrict__ pt,
                                                   const float* __restrict__ bscale,
                                                   float* __restrict__ outp) {
    extern __shared__ char smem_raw[];
    const unsigned int sbase = (unsigned int)__cvta_generic_to_shared(smem_raw);
    const int tid = threadIdx.x, lane = tid & 31, wid = tid >> 5;
    const int wm = wid & 3, wn = wid >> 2;
    const int row0 = blockIdx.y * 128, col0 = blockIdx.x * 128;
    const int z = blockIdx.z;

    const __nv_bfloat16* A  = z ? g_a3 : g_a2;
    const __nv_bfloat16* Bw = z ? g_w3 : g_w2;
    const float* basep = z ? pt : g_tsaug;
    float* op = outp + (size_t)z * NROWS * DD;

    float acc[2][8][4];
#pragma unroll
    for (int i = 0; i < 2; i++)
#pragma unroll
        for (int j = 0; j < 8; j++)
#pragma unroll
            for (int q = 0; q < 4; q++) acc[i][j][q] = 0.0f;

    gemm_core(A, DD, Bw, row0, col0, 1024, sbase, acc);

    float blend = 0.35f / (1.0f + expf(-bscale[0]));
#pragma unroll
    for (int i = 0; i < 2; i++) {
        int rb = row0 + wm * 32 + i * 16 + (lane >> 2);
#pragma unroll
        for (int h = 0; h < 2; h++) {
            int r = rb + h * 8;
            float lb = blend * g_gate[r];
#pragma unroll
            for (int j = 0; j < 8; j++) {
                int c = col0 + wn * 64 + j * 8 + (lane & 3) * 2;
                float v0 = acc[i][j][h * 2], v1 = acc[i][j][h * 2 + 1];
                float2 b2 = *(const float2*)(basep + (size_t)r * DD + c);
                float2 o = make_float2(b2.x + lb * v0, b2.y + lb * v1);
                *(float2*)(op + (size_t)r * DD + c) = o;
            }
        }
    }
}

// ---------------- launch ----------------
extern "C" void kernel_launch(void* const* d_in, const int* in_sizes, int n_in,
                              void* d_out, int out_size) {
    const float* pt   = (const float*)d_in[0];
    const float* ts   = (const float*)d_in[1];
    const float* pos  = (const float*)d_in[2];
    const float* cent = (const float*)d_in[3];
    const float* stab = (const float*)d_in[4];
    const float* aw   = (const float*)d_in[5];
    const float* ab   = (const float*)d_in[6];
    const float* ta   = (const float*)d_in[7];
    const float* tb   = (const float*)d_in[8];
    const float* og   = (const float*)d_in[9];
    const float* ob   = (const float*)d_in[10];
    const float* tg   = (const float*)d_in[11];
    const float* tb2  = (const float*)d_in[12];
    const float* pg   = (const float*)d_in[13];
    const float* pb   = (const float*)d_in[14];
    const float* sW   = (const float*)d_in[15];
    const float* sb   = (const float*)d_in[16];
    const float* tuW  = (const float*)d_in[17];
    const float* puW  = (const float*)d_in[18];
    const float* bs   = (const float*)d_in[19];
    float* out = (float*)d_out;

    cudaFuncSetAttribute(k_gemm1,  cudaFuncAttributeMaxDynamicSharedMemorySize, GEMM_SMEM);
    cudaFuncSetAttribute(k_gemm23, cudaFuncAttributeMaxDynamicSharedMemorySize, GEMM_SMEM);

    // one launch converts all three weight matrices
    k_cvtall<<<CVT_G1 + 2 * CVT_G2, 256>>>(sW, tuW, puW);

    k_scores<<<NROWS / 8, 256>>>(pt, aw, ab);
    k_top3<<<BB, 256>>>(pos);
    k_basis<<<BB * KA * MM, 128>>>(pt, cent, ta);
    k_mix<<<BB * KA, 128>>>(pos);
    k_translate<<<BB * KA * MM, 128>>>(tb);
    k_tcombine<<<BB * KA, 256>>>();
    k_rows<<<NROWS, 256>>>(ts, pt, pos, stab, og, ob, tg, tb2, pg, pb);

    k_gemm1<<<dim3(8, 256), 256, GEMM_SMEM>>>(sb, sW + (size_t)2048 * DD);
    k_pool<<<NROWS, 256>>>();
    k_gemm23<<<dim3(8, 256, 2), 256, GEMM_SMEM>>>(pt, bs, out);
}

// round 16
// speedup vs baseline: 1.4014x; 1.0132x over previous
#include <cuda_runtime.h>
#include <cuda_bf16.h>
#include <cstdint>

#define BB 8
#define SS 4096
#define DD 1024
#define MM 32
#define KA 3
#define RR 64
#define NROWS (BB*SS)

// ---------------- scratch (device globals; no allocations allowed) ----------------
__device__ float g_scores[NROWS];
__device__ int   g_aidx[BB*KA];
__device__ float g_apos[BB*KA];
__device__ float g_logits[BB*KA*MM];
__device__ float g_ua[BB*KA*MM*RR];
__device__ float g_w[BB*KA*MM];
__device__ float g_low[BB*KA*RR];
__device__ float g_Z[BB*KA];
__device__ float g_transp[BB*KA*MM*DD];
__device__ float g_trans[BB*KA*DD];
__device__ float g_tsaug[(size_t)NROWS*DD];
__device__ float g_gate[NROWS];
__device__ __align__(16) __nv_bfloat16 g_sharedh[(size_t)NROWS*DD];  // shared (bf16)
__device__ __align__(16) __nv_bfloat16 g_cat[(size_t)NROWS*2*DD];    // [tsn|ptn] bf16
__device__ __align__(16) __nv_bfloat16 g_a2[(size_t)NROWS*DD];
__device__ __align__(16) __nv_bfloat16 g_a3[(size_t)NROWS*DD];
__device__ __align__(16) __nv_bfloat16 g_w1[(size_t)2048*DD];        // shared_W[0:2048] bf16
__device__ __align__(16) __nv_bfloat16 g_w2[(size_t)DD*DD];          // ts_up_W bf16
__device__ __align__(16) __nv_bfloat16 g_w3[(size_t)DD*DD];          // pt_up_W bf16

// ---------------- cp.async helpers ----------------
__device__ __forceinline__ void cp16s(unsigned int dst_sh, const void* src) {
    asm volatile("cp.async.cg.shared.global [%0], [%1], 16;\n" :: "r"(dst_sh), "l"(src));
}
#define CP_COMMIT() asm volatile("cp.async.commit_group;\n" ::: "memory")
#define CP_WAIT1()  asm volatile("cp.async.wait_group 1;\n" ::: "memory")

// ---------------- all weight fp32 -> bf16 in ONE launch ----------------
#define CVT_G1 (2048*DD/4/256)   // 2048 blocks
#define CVT_G2 (DD*DD/4/256)     // 1024 blocks
__global__ void __launch_bounds__(256) k_cvtall(const float* __restrict__ sW,
                                                const float* __restrict__ tuW,
                                                const float* __restrict__ puW) {
    int blk = blockIdx.x;
    const float* src;
    __nv_bfloat16* dst;
    int i;
    if (blk < CVT_G1)               { src = sW;  dst = g_w1; i = blk * 256 + threadIdx.x; }
    else if (blk < CVT_G1 + CVT_G2) { src = tuW; dst = g_w2; i = (blk - CVT_G1) * 256 + threadIdx.x; }
    else                            { src = puW; dst = g_w3; i = (blk - CVT_G1 - CVT_G2) * 256 + threadIdx.x; }
    float4 v = ((const float4*)src)[i];
    __nv_bfloat162* o = (__nv_bfloat162*)dst + (size_t)i * 2;
    o[0] = __floats2bfloat162_rn(v.x, v.y);
    o[1] = __floats2bfloat162_rn(v.z, v.w);
}

// ---------------- K0: anchor scores ----------------
__global__ void __launch_bounds__(256) k_scores(const float* __restrict__ pt,
                                                const float* __restrict__ aw,
                                                const float* __restrict__ ab) {
    int gw = (blockIdx.x * blockDim.x + threadIdx.x) >> 5;
    int lane = threadIdx.x & 31;
    if (gw >= NROWS) return;
    const float4* p = (const float4*)(pt + (size_t)gw * DD);
    const float4* w = (const float4*)aw;
    float s = 0.f;
#pragma unroll
    for (int i = 0; i < 8; i++) {
        float4 a = p[lane + 32 * i];
        float4 b = w[lane + 32 * i];
        s += a.x * b.x + a.y * b.y + a.z * b.z + a.w * b.w;
    }
#pragma unroll
    for (int o = 16; o; o >>= 1) s += __shfl_down_sync(0xffffffffu, s, o);
    if (!lane) g_scores[gw] = s + ab[0];
}

// ---------------- K1: top-3 per batch ----------------
__global__ void k_top3(const float* __restrict__ pos) {
    __shared__ float sv[256];
    __shared__ int   si[256];
    __shared__ int   chosen[KA];
    int b = blockIdx.x, tid = threadIdx.x;
    const float* sc = g_scores + b * SS;
    for (int k = 0; k < KA; k++) {
        float bv = -3.4e38f; int bi = SS;
        for (int s = tid; s < SS; s += 256) {
            bool used = false;
            for (int j = 0; j < k; j++) used |= (chosen[j] == s);
            if (used) continue;
            float v = sc[s];
            if (v > bv || (v == bv && s < bi)) { bv = v; bi = s; }
        }
        sv[tid] = bv; si[tid] = bi;
        __syncthreads();
        for (int o = 128; o; o >>= 1) {
            if (tid < o) {
                if (sv[tid + o] > sv[tid] || (sv[tid + o] == sv[tid] && si[tid + o] < si[tid])) {
                    sv[tid] = sv[tid + o]; si[tid] = si[tid + o];
                }
            }
            __syncthreads();
        }
        if (tid == 0) {
            chosen[k] = si[0];
            g_aidx[b * KA + k] = si[0];
            g_apos[b * KA + k] = pos[si[0]];
        }
        __syncthreads();
    }
}

// ---------------- K2: per (b,k,m): cosine logit + u_a  (256 threads, 4-way split) ----------------
__global__ void __launch_bounds__(256) k_basis(const float* __restrict__ pt,
                                               const float* __restrict__ cent,
                                               const float* __restrict__ ta) {
    __shared__ float av[DD];
    __shared__ float r1[256], r2[256], r3[256];
    int id = blockIdx.x;
    int m = id % MM, bk = id / MM;
    int b = bk / KA;
    int tid = threadIdx.x;
    const float* prow = pt + ((size_t)b * SS + g_aidx[bk]) * DD;
    const float* crow = cent + (size_t)m * DD;
    float pa = 0.f, pc = 0.f, pd = 0.f;
    for (int d = tid; d < DD; d += 256) {
        float a = prow[d], c = crow[d];
        av[d] = a; pa += a * a; pc += c * c; pd += a * c;
    }
    r1[tid] = pa; r2[tid] = pc; r3[tid] = pd;
    __syncthreads();
    for (int o = 128; o; o >>= 1) {
        if (tid < o) { r1[tid] += r1[tid + o]; r2[tid] += r2[tid + o]; r3[tid] += r3[tid + o]; }
        __syncthreads();
    }
    if (tid == 0) {
        float na = sqrtf(r1[0]), nc = sqrtf(r2[0]);
        g_logits[id] = r3[0] / (fmaxf(na, 1e-6f) * fmaxf(nc, 1e-6f));
    }
    __syncthreads();
    int r = tid & 63, h = tid >> 6;          // h in 0..3, each covers 256 d
    const float* tap = ta + (size_t)m * DD * RR + r;
    float u = 0.f;
    int d0 = h * 256;
#pragma unroll 8
    for (int d = d0; d < d0 + 256; d++) u += av[d] * tap[(size_t)d * RR];
    r1[tid] = u;
    __syncthreads();
    if (h == 0) g_ua[(size_t)id * RR + r] = (r1[r] + r1[r + 64]) + (r1[r + 128] + r1[r + 192]);
}

// ---------------- K3: per (b,k): softmax, low, spread normalizer ----------------
__global__ void __launch_bounds__(128) k_mix(const float* __restrict__ pos) {
    __shared__ float w[MM];
    __shared__ float red[128];
    int bk = blockIdx.x, tid = threadIdx.x;
    if (tid == 0) {
        float mx = -3.4e38f;
        for (int m = 0; m < MM; m++) mx = fmaxf(mx, g_logits[bk * MM + m]);
        float ssum = 0.f;
        for (int m = 0; m < MM; m++) { float e = expf(g_logits[bk * MM + m] - mx); w[m] = e; ssum += e; }
        float inv = 1.0f / ssum;
        for (int m = 0; m < MM; m++) w[m] *= inv;
    }
    __syncthreads();
    if (tid < MM) g_w[bk * MM + tid] = w[tid];
    if (tid < RR) {
        float lo = 0.f;
        for (int m = 0; m < MM; m++) lo += w[m] * g_ua[(size_t)(bk * MM + m) * RR + tid];
        g_low[bk * RR + tid] = lo;
    }
    float p = g_apos[bk];
    float z = 0.f;
    for (int s = tid; s < SS; s += 128) {
        float d = fabsf(pos[s] - p);
        if (d <= 8.0f) z += expf(-d * 0.125f);
    }
    red[tid] = z;
    __syncthreads();
    for (int o = 64; o; o >>= 1) { if (tid < o) red[tid] += red[tid + o]; __syncthreads(); }
    if (tid == 0) g_Z[bk] = red[0];
}

// ---------------- K4: per (b,k,m): partial translated (256 threads) ----------------
__global__ void __launch_bounds__(256) k_translate(const float* __restrict__ tb) {
    __shared__ float low[RR];
    __shared__ float wv;
    int id = blockIdx.x;
    int m = id % MM, bk = id / MM;
    int tid = threadIdx.x;
    if (tid < RR) low[tid] = g_low[bk * RR + tid];
    if (tid == 0) wv = g_w[bk * MM + m];
    __syncthreads();
    float wloc = wv;
    const float4* base = (const float4*)(tb + (size_t)m * DD * RR);
#pragma unroll
    for (int j = 0; j < 4; j++) {
        int d = tid + 256 * j;
        const float4* rp = base + (size_t)d * (RR / 4);
        float acc = 0.f;
#pragma unroll
        for (int i = 0; i < 16; i++) {
            float4 v = rp[i];
            acc += low[4 * i] * v.x + low[4 * i + 1] * v.y + low[4 * i + 2] * v.z + low[4 * i + 3] * v.w;
        }
        g_transp[(size_t)id * DD + d] = wloc * acc;
    }
}

__global__ void __launch_bounds__(256) k_tcombine() {
    int bk = blockIdx.x, tid = threadIdx.x;
    for (int d = tid; d < DD; d += 256) {
        float s = 0.f;
        for (int m = 0; m < MM; m++) s += g_transp[(size_t)(bk * MM + m) * DD + d];
        g_trans[bk * DD + d] = s;
    }
}

// ---------------- block reduce helper ----------------
__device__ __forceinline__ float2 bred2(float2 v, float* red) {
    int tid = threadIdx.x;
#pragma unroll
    for (int o = 16; o; o >>= 1) {
        v.x += __shfl_down_sync(0xffffffffu, v.x, o);
        v.y += __shfl_down_sync(0xffffffffu, v.y, o);
    }
    if ((tid & 31) == 0) { red[tid >> 5] = v.x; red[8 + (tid >> 5)] = v.y; }
    __syncthreads();
    if (tid == 0) {
        float a = 0.f, b = 0.f;
        for (int i = 0; i < 8; i++) { a += red[i]; b += red[8 + i]; }
        red[0] = a; red[8] = b;
    }
    __syncthreads();
    float2 r = make_float2(red[0], red[8]);
    __syncthreads();
    return r;
}

// ---------------- K5: fused row kernel (anchor update + 3 LNs + gate) ----------------
__global__ void __launch_bounds__(256) k_rows(
    const float* __restrict__ ts, const float* __restrict__ pt,
    const float* __restrict__ pos, const float* __restrict__ stab,
    const float* __restrict__ og, const float* __restrict__ ob,
    const float* __restrict__ tg, const float* __restrict__ tb2,
    const float* __restrict__ pg, const float* __restrict__ pb) {
    __shared__ float red[16];
    int row = blockIdx.x;
    int b = row / SS, s = row % SS;
    int tid = threadIdx.x;
    size_t base = (size_t)row * DD;
    float4 tsv = ((const float4*)(ts + base))[tid];
    float4 ptv = ((const float4*)(pt + base))[tid];
    float ps = pos[s];
    float4 upd = make_float4(0.f, 0.f, 0.f, 0.f);
#pragma unroll
    for (int k = 0; k < KA; k++) {
        int bk = b * KA + k;
        float dist = fabsf(ps - g_apos[bk]);
        if (dist <= 8.0f) {
            float c = expf(-dist * 0.125f) / g_Z[bk];
            float4 t = ((const float4*)(g_trans + (size_t)bk * DD))[tid];
            upd.x += c * t.x; upd.y += c * t.y; upd.z += c * t.z; upd.w += c * t.w;
        }
    }
    float4 x = make_float4(tsv.x + upd.x, tsv.y + upd.y, tsv.z + upd.z, tsv.w + upd.w);
    const float invD = 1.0f / DD;
    float2 s1 = bred2(make_float2(x.x + x.y + x.z + x.w,
                                  x.x * x.x + x.y * x.y + x.z * x.z + x.w * x.w), red);
    float mu = s1.x * invD;
    float var = s1.y * invD - mu * mu;
    float rs = rsqrtf(var + 1e-5f);
    float4 gv = ((const float4*)og)[tid], bv = ((const float4*)ob)[tid];
    float4 aug;
    aug.x = (x.x - mu) * rs * gv.x + bv.x;
    aug.y = (x.y - mu) * rs * gv.y + bv.y;
    aug.z = (x.z - mu) * rs * gv.z + bv.z;
    aug.w = (x.w - mu) * rs * gv.w + bv.w;
    ((float4*)(g_tsaug + base))[tid] = aug;
    float2 s2 = bred2(make_float2(aug.x + aug.y + aug.z + aug.w,
                                  aug.x * aug.x + aug.y * aug.y + aug.z * aug.z + aug.w * aug.w), red);
    float mu2 = s2.x * invD;
    float rs2 = rsqrtf(s2.y * invD - mu2 * mu2 + 1e-5f);
    float4 gv2 = ((const float4*)tg)[tid], bv2 = ((const float4*)tb2)[tid];
    float4 tn;
    tn.x = (aug.x - mu2) * rs2 * gv2.x + bv2.x;
    tn.y = (aug.y - mu2) * rs2 * gv2.y + bv2.y;
    tn.z = (aug.z - mu2) * rs2 * gv2.z + bv2.z;
    tn.w = (aug.w - mu2) * rs2 * gv2.w + bv2.w;
    float2 s3 = bred2(make_float2(ptv.x + ptv.y + ptv.z + ptv.w,
                                  ptv.x * ptv.x + ptv.y * ptv.y + ptv.z * ptv.z + ptv.w * ptv.w), red);
    float mu3 = s3.x * invD;
    float rs3 = rsqrtf(s3.y * invD - mu3 * mu3 + 1e-5f);
    float4 gv3 = ((const float4*)pg)[tid], bv3 = ((const float4*)pb)[tid];
    float4 pn;
    pn.x = (ptv.x - mu3) * rs3 * gv3.x + bv3.x;
    pn.y = (ptv.y - mu3) * rs3 * gv3.y + bv3.y;
    pn.z = (ptv.z - mu3) * rs3 * gv3.z + bv3.z;
    pn.w = (ptv.w - mu3) * rs3 * gv3.w + bv3.w;
    {
        __nv_bfloat162* ct = (__nv_bfloat162*)(g_cat + (size_t)row * 2 * DD) + tid * 2;
        ct[0] = __floats2bfloat162_rn(tn.x, tn.y);
        ct[1] = __floats2bfloat162_rn(tn.z, tn.w);
        __nv_bfloat162* cp2 = (__nv_bfloat162*)(g_cat + (size_t)row * 2 * DD + DD) + tid * 2;
        cp2[0] = __floats2bfloat162_rn(pn.x, pn.y);
        cp2[1] = __floats2bfloat162_rn(pn.z, pn.w);
    }
    float2 s4 = bred2(make_float2(tn.x * pn.x + tn.y * pn.y + tn.z * pn.z + tn.w * pn.w,
                                  tn.x * tn.x + tn.y * tn.y + tn.z * tn.z + tn.w * tn.w), red);
    float2 s5 = bred2(make_float2(pn.x * pn.x + pn.y * pn.y + pn.z * pn.z + pn.w * pn.w, 0.f), red);
    if (tid == 0) {
        float cosv = s4.x / (fmaxf(sqrtf(s4.y), 1e-6f) * fmaxf(sqrtf(s5.x), 1e-6f));
        float ag = 0.5f * (1.0f + cosv);
        float z = (ag - 0.72f) / 0.2f;
        float focus = 0.2f + 0.8f * expf(-0.5f * z * z);
        g_gate[row] = ag * focus * stab[row];
    }
}

// ---------------- K7: causal pool (bf16 shared) + form bf16 GEMM inputs ----------------
__global__ void __launch_bounds__(256) k_pool() {
    int row = blockIdx.x;
    int b = row / SS, s = row % SS;
    int tid = threadIdx.x;
    size_t base = (size_t)row * DD;
    int s1 = s - 1; if (s1 < 0) s1 = 0;
    int s2 = s - 2; if (s2 < 0) s2 = 0;
    size_t b1 = ((size_t)b * SS + s1) * DD;
    size_t b2 = ((size_t)b * SS + s2) * DD;
    const __nv_bfloat162* h0 = (const __nv_bfloat162*)(g_sharedh + base) + tid * 2;
    const __nv_bfloat162* h1 = (const __nv_bfloat162*)(g_sharedh + b1) + tid * 2;
    const __nv_bfloat162* h2 = (const __nv_bfloat162*)(g_sharedh + b2) + tid * 2;
    float2 a0 = __bfloat1622float2(h0[0]), a1 = __bfloat1622float2(h0[1]);
    float2 c0 = __bfloat1622float2(h1[0]), c1 = __bfloat1622float2(h1[1]);
    float2 e0 = __bfloat1622float2(h2[0]), e1 = __bfloat1622float2(h2[1]);
    float4 pl;
    pl.x = (a0.x + c0.x + e0.x) / 3.0f;
    pl.y = (a0.y + c0.y + e0.y) / 3.0f;
    pl.z = (a1.x + c1.x + e1.x) / 3.0f;
    pl.w = (a1.y + c1.y + e1.y) / 3.0f;
    const __nv_bfloat162* ct = (const __nv_bfloat162*)(g_cat + (size_t)row * 2 * DD) + tid * 2;
    const __nv_bfloat162* cp2 = (const __nv_bfloat162*)(g_cat + (size_t)row * 2 * DD + DD) + tid * 2;
    float2 t01 = __bfloat1622float2(ct[0]);
    float2 t23 = __bfloat1622float2(ct[1]);
    float2 p01 = __bfloat1622float2(cp2[0]);
    float2 p23 = __bfloat1622float2(cp2[1]);
    __nv_bfloat162* o2 = (__nv_bfloat162*)(g_a2 + base) + tid * 2;
    o2[0] = __floats2bfloat162_rn(pl.x - t01.x, pl.y - t01.y);
    o2[1] = __floats2bfloat162_rn(pl.z - t23.x, pl.w - t23.y);
    __nv_bfloat162* o3 = (__nv_bfloat162*)(g_a3 + base) + tid * 2;
    o3[0] = __floats2bfloat162_rn(pl.x - p01.x, pl.y - p01.y);
    o3[1] = __floats2bfloat162_rn(pl.z - p23.x, pl.w - p23.y);
}

// ---------------- raw mma.sync bf16 GEMM core (R14 config) ----------------
#define STG_BYTES 32768          // 16KB A + 16KB B per stage
#define GEMM_SMEM (3*STG_BYTES)  // 98304 -> 2 CTAs/SM

__device__ __forceinline__ void gemm_core(const __nv_bfloat16* __restrict__ A, int lda,
                                          const __nv_bfloat16* __restrict__ Bw,
                                          int row0, int col0, int Ktot,
                                          unsigned int sbase, float (&acc)[2][8][4]) {
    const int tid = threadIdx.x, lane = tid & 31, wid = tid >> 5;
    const int wm = wid & 3, wn = wid >> 2;

    auto load_stage = [&](int s, int kt) {
        unsigned int ab = sbase + s * STG_BYTES;
        unsigned int bb = ab + 16384;
#pragma unroll
        for (int p = 0; p < 4; p++) {
            int id = tid + 256 * p;
            int m = id >> 3, kc = id & 7;
            cp16s(ab + m * 128 + ((kc ^ (m & 7)) << 4),
                  A + (size_t)(row0 + m) * lda + kt * 64 + kc * 8);
            int k = id >> 4, nc = id & 15;
            cp16s(bb + k * 256 + ((nc ^ (k & 15)) << 4),
                  Bw + (size_t)(kt * 64 + k) * DD + col0 + nc * 8);
        }
        CP_COMMIT();
    };

    const int nIter = Ktot >> 6;
    load_stage(0, 0);
    load_stage(1, 1);

    int st = 0;
    for (int it = 0; it < nIter; it++) {
        CP_WAIT1();
        __syncthreads();
        int nf = it + 2;
        if (nf < nIter) load_stage(nf - (nf / 3) * 3, nf);
        else CP_COMMIT();
        unsigned int ab = sbase + st * STG_BYTES;
        unsigned int bb = ab + 16384;
#pragma unroll
        for (int kk = 0; kk < 4; kk++) {
            unsigned int af[2][4], bf[8][2];
#pragma unroll
            for (int j = 0; j < 4; j++) {
                int r = kk * 16 + (lane & 7) + ((lane >> 3) & 1) * 8;
                int nc = wn * 8 + j * 2 + (lane >> 4);
                unsigned int addr = bb + r * 256 + ((nc ^ (r & 15)) << 4);
                asm volatile("ldmatrix.sync.aligned.m8n8.x4.trans.shared.b16 {%0,%1,%2,%3}, [%4];"
                    : "=r"(bf[2*j][0]), "=r"(bf[2*j][1]), "=r"(bf[2*j+1][0]), "=r"(bf[2*j+1][1])
                    : "r"(addr));
            }
#pragma unroll
            for (int i = 0; i < 2; i++) {
                int r = wm * 32 + i * 16 + (lane & 15);
                int kc = kk * 2 + (lane >> 4);
                unsigned int addr = ab + r * 128 + ((kc ^ (r & 7)) << 4);
                asm volatile("ldmatrix.sync.aligned.m8n8.x4.shared.b16 {%0,%1,%2,%3}, [%4];"
                    : "=r"(af[i][0]), "=r"(af[i][1]), "=r"(af[i][2]), "=r"(af[i][3])
                    : "r"(addr));
            }
#pragma unroll
            for (int i = 0; i < 2; i++)
#pragma unroll
                for (int j = 0; j < 8; j++)
                    asm volatile("mma.sync.aligned.m16n8k16.row.col.f32.bf16.bf16.f32 "
                        "{%0,%1,%2,%3}, {%4,%5,%6,%7}, {%8,%9}, {%0,%1,%2,%3};"
                        : "+f"(acc[i][j][0]), "+f"(acc[i][j][1]), "+f"(acc[i][j][2]), "+f"(acc[i][j][3])
                        : "r"(af[i][0]), "r"(af[i][1]), "r"(af[i][2]), "r"(af[i][3]),
                          "r"(bf[j][0]), "r"(bf[j][1]));
        }
        st++; if (st == 3) st = 0;
    }
}

// MODE1: shared = [tsn|ptn] @ W1 + bias + gate*wlast  (K=2048), bf16 out to g_sharedh
__global__ void __launch_bounds__(256, 2) k_gemm1(const float* __restrict__ bias,
                                                  const float* __restrict__ wlast) {
    extern __shared__ char smem_raw[];
    const unsigned int sbase = (unsigned int)__cvta_generic_to_shared(smem_raw);
    const int tid = threadIdx.x, lane = tid & 31, wid = tid >> 5;
    const int wm = wid & 3, wn = wid >> 2;
    const int row0 = blockIdx.y * 128, col0 = blockIdx.x * 128;

    float acc[2][8][4];
#pragma unroll
    for (int i = 0; i < 2; i++)
#pragma unroll
        for (int j = 0; j < 8; j++)
#pragma unroll
            for (int q = 0; q < 4; q++) acc[i][j][q] = 0.0f;

    gemm_core(g_cat, 2 * DD, g_w1, row0, col0, 2048, sbase, acc);

#pragma unroll
    for (int i = 0; i < 2; i++) {
        int rb = row0 + wm * 32 + i * 16 + (lane >> 2);
#pragma unroll
        for (int h = 0; h < 2; h++) {
            int r = rb + h * 8;
            float g = g_gate[r];
#pragma unroll
            for (int j = 0; j < 8; j++) {
                int c = col0 + wn * 64 + j * 8 + (lane & 3) * 2;
                float v0 = acc[i][j][h * 2], v1 = acc[i][j][h * 2 + 1];
                float2 bi = *(const float2*)(bias + c);
                float2 wl = *(const float2*)(wlast + c);
                *(__nv_bfloat162*)(g_sharedh + (size_t)r * DD + c) =
                    __floats2bfloat162_rn(v0 + bi.x + g * wl.x, v1 + bi.y + g * wl.y);
            }
        }
    }
}

// MODE2+3 merged (blockIdx.z): z=0: ts_out = tsaug + lb*(a2@w2); z=1: pt_out = pt + lb*(a3@w3)
__global__ void __launch_bounds__(256, 2) k_gemm23(const float* __restrict__ pt,
                                                   const float* __restrict__ bscale,
                                                   float* __restrict__ outp) {
    extern __shared__ char smem_raw[];
    const unsigned int sbase = (unsigned int)__cvta_generic_to_shared(smem_raw);
    const int tid = threadIdx.x, lane = tid & 31, wid = tid >> 5;
    const int wm = wid & 3, wn = wid >> 2;
    const int row0 = blockIdx.y * 128, col0 = blockIdx.x * 128;
    const int z = blockIdx.z;

    const __nv_bfloat16* A  = z ? g_a3 : g_a2;
    const __nv_bfloat16* Bw = z ? g_w3 : g_w2;
    const float* basep = z ? pt : g_tsaug;
    float* op = outp + (size_t)z * NROWS * DD;

    float acc[2][8][4];
#pragma unroll
    for (int i = 0; i < 2; i++)
#pragma unroll
        for (int j = 0; j < 8; j++)
#pragma unroll
            for (int q = 0; q < 4; q++) acc[i][j][q] = 0.0f;

    gemm_core(A, DD, Bw, row0, col0, 1024, sbase, acc);

    float blend = 0.35f / (1.0f + expf(-bscale[0]));
#pragma unroll
    for (int i = 0; i < 2; i++) {
        int rb = row0 + wm * 32 + i * 16 + (lane >> 2);
#pragma unroll
        for (int h = 0; h < 2; h++) {
            int r = rb + h * 8;
            float lb = blend * g_gate[r];
#pragma unroll
            for (int j = 0; j < 8; j++) {
                int c = col0 + wn * 64 + j * 8 + (lane & 3) * 2;
                float v0 = acc[i][j][h * 2], v1 = acc[i][j][h * 2 + 1];
                float2 b2 = *(const float2*)(basep + (size_t)r * DD + c);
                float2 o = make_float2(b2.x + lb * v0, b2.y + lb * v1);
                *(float2*)(op + (size_t)r * DD + c) = o;
            }
        }
    }
}

// ---------------- launch ----------------
extern "C" void kernel_launch(void* const* d_in, const int* in_sizes, int n_in,
                              void* d_out, int out_size) {
    const float* pt   = (const float*)d_in[0];
    const float* ts   = (const float*)d_in[1];
    const float* pos  = (const float*)d_in[2];
    const float* cent = (const float*)d_in[3];
    const float* stab = (const float*)d_in[4];
    const float* aw   = (const float*)d_in[5];
    const float* ab   = (const float*)d_in[6];
    const float* ta   = (const float*)d_in[7];
    const float* tb   = (const float*)d_in[8];
    const float* og   = (const float*)d_in[9];
    const float* ob   = (const float*)d_in[10];
    const float* tg   = (const float*)d_in[11];
    const float* tb2  = (const float*)d_in[12];
    const float* pg   = (const float*)d_in[13];
    const float* pb   = (const float*)d_in[14];
    const float* sW   = (const float*)d_in[15];
    const float* sb   = (const float*)d_in[16];
    const float* tuW  = (const float*)d_in[17];
    const float* puW  = (const float*)d_in[18];
    const float* bs   = (const float*)d_in[19];
    float* out = (float*)d_out;

    cudaFuncSetAttribute(k_gemm1,  cudaFuncAttributeMaxDynamicSharedMemorySize, GEMM_SMEM);
    cudaFuncSetAttribute(k_gemm23, cudaFuncAttributeMaxDynamicSharedMemorySize, GEMM_SMEM);

    k_cvtall<<<CVT_G1 + 2 * CVT_G2, 256>>>(sW, tuW, puW);

    k_scores<<<NROWS / 8, 256>>>(pt, aw, ab);
    k_top3<<<BB, 256>>>(pos);
    k_basis<<<BB * KA * MM, 256>>>(pt, cent, ta);
    k_mix<<<BB * KA, 128>>>(pos);
    k_translate<<<BB * KA * MM, 256>>>(tb);
    k_tcombine<<<BB * KA, 256>>>();
    k_rows<<<NROWS, 256>>>(ts, pt, pos, stab, og, ob, tg, tb2, pg, pb);

    k_gemm1<<<dim3(8, 256), 256, GEMM_SMEM>>>(sb, sW + (size_t)2048 * DD);
    k_pool<<<NROWS, 256>>>();
    k_gemm23<<<dim3(8, 256, 2), 256, GEMM_SMEM>>>(pt, bs, out);
}